// round 11
// baseline (speedup 1.0000x reference)
#include <cuda_runtime.h>
#include <cuda_bf16.h>
#include <math.h>
#include <stdint.h>

// ---------------------------------------------------------------------------
// GPT-2 small forward: B=8, T=1024, E=768, H=12, D=64, L=12, V=50304
// Round 11: GEMM 256x128 CTA tile / 512 threads / 16 warps, warp tile 64x32
// (4 warps per SMSP to fill the HMMA issue slots). 2 stages x 96KB.
// Attention = round-4 proven config.
// ---------------------------------------------------------------------------

#define NTOK   8192
#define EDIM   768
#define E3     2304
#define E4     3072
#define NHEAD  12
#define HDIM   64
#define NLAYER 12
#define VOCAB  50304
#define NBATCH 8
#define TSEQ   1024

// ---------------- device scratch (allocation-free) ----------------
__device__ __align__(16) float          g_x    [NTOK * EDIM];
__device__ __align__(16) float          g_xf   [NBATCH * EDIM];
__device__ __align__(16) __nv_bfloat16  g_h_hi  [NTOK * EDIM];
__device__ __align__(16) __nv_bfloat16  g_h_lo  [NTOK * EDIM];
__device__ __align__(16) __nv_bfloat16  g_qkv_hi[NTOK * E3];
__device__ __align__(16) __nv_bfloat16  g_qkv_lo[NTOK * E3];
__device__ __align__(16) __nv_bfloat16  g_att_hi[NTOK * EDIM];
__device__ __align__(16) __nv_bfloat16  g_att_lo[NTOK * EDIM];
__device__ __align__(16) __nv_bfloat16  g_a1_hi [NTOK * E4];
__device__ __align__(16) __nv_bfloat16  g_a1_lo [NTOK * E4];
__device__ __align__(16) __nv_bfloat16  g_wqkv_hi[NLAYER * E3 * EDIM];
__device__ __align__(16) __nv_bfloat16  g_wqkv_lo[NLAYER * E3 * EDIM];
__device__ __align__(16) __nv_bfloat16  g_wprj_hi[NLAYER * EDIM * EDIM];
__device__ __align__(16) __nv_bfloat16  g_wprj_lo[NLAYER * EDIM * EDIM];
__device__ __align__(16) __nv_bfloat16  g_wc1_hi [NLAYER * E4 * EDIM];
__device__ __align__(16) __nv_bfloat16  g_wc1_lo [NLAYER * E4 * EDIM];
__device__ __align__(16) __nv_bfloat16  g_wc2_hi [NLAYER * EDIM * E4];
__device__ __align__(16) __nv_bfloat16  g_wc2_lo [NLAYER * EDIM * E4];

// ---------------- helpers ----------------
__device__ __forceinline__ uint32_t smem_u32(const void* p) {
    uint32_t a;
    asm("{ .reg .u64 t; cvta.to.shared.u64 t, %1; cvt.u32.u64 %0, t; }"
        : "=r"(a) : "l"(p));
    return a;
}
__device__ __forceinline__ void cpa16(uint32_t dst, const void* src) {
    asm volatile("cp.async.cg.shared.global [%0], [%1], 16;" :: "r"(dst), "l"(src));
}
__device__ __forceinline__ void cpa_commit() {
    asm volatile("cp.async.commit_group;" ::: "memory");
}
template<int N> __device__ __forceinline__ void cpa_wait() {
    asm volatile("cp.async.wait_group %0;" :: "n"(N) : "memory");
}
__device__ __forceinline__ void ldsm_x4(uint32_t* r, uint32_t a) {
    asm volatile("ldmatrix.sync.aligned.m8n8.x4.shared.b16 {%0,%1,%2,%3}, [%4];"
        : "=r"(r[0]), "=r"(r[1]), "=r"(r[2]), "=r"(r[3]) : "r"(a));
}
__device__ __forceinline__ void ldsm_x2(uint32_t* r, uint32_t a) {
    asm volatile("ldmatrix.sync.aligned.m8n8.x2.shared.b16 {%0,%1}, [%2];"
        : "=r"(r[0]), "=r"(r[1]) : "r"(a));
}
__device__ __forceinline__ void ldsm_x2t(uint32_t* r, uint32_t a) {
    asm volatile("ldmatrix.sync.aligned.m8n8.x2.trans.shared.b16 {%0,%1}, [%2];"
        : "=r"(r[0]), "=r"(r[1]) : "r"(a));
}
__device__ __forceinline__ void mma_bf16(float* c, const uint32_t* a,
                                         const uint32_t* b) {
    asm volatile(
        "mma.sync.aligned.m16n8k16.row.col.f32.bf16.bf16.f32 "
        "{%0,%1,%2,%3}, {%4,%5,%6,%7}, {%8,%9}, {%0,%1,%2,%3};"
        : "+f"(c[0]), "+f"(c[1]), "+f"(c[2]), "+f"(c[3])
        : "r"(a[0]), "r"(a[1]), "r"(a[2]), "r"(a[3]), "r"(b[0]), "r"(b[1]));
}
__device__ __forceinline__ float gelu_exact(float v) {
    return 0.5f * v * (1.0f + erff(v * 0.70710678118654752f));
}

// ---------------------------------------------------------------------------
// Fused weight convert: all four weight groups in ONE launch.
// ---------------------------------------------------------------------------
__device__ __forceinline__ void cvt4(const float* w, __nv_bfloat16* hi,
                                     __nv_bfloat16* lo, int i) {
    float4 v = ((const float4*)w)[i];
    __nv_bfloat16 h0 = __float2bfloat16(v.x), h1 = __float2bfloat16(v.y);
    __nv_bfloat16 h2 = __float2bfloat16(v.z), h3 = __float2bfloat16(v.w);
    __nv_bfloat162 hh0, hh1, ll0, ll1;
    hh0.x = h0; hh0.y = h1; hh1.x = h2; hh1.y = h3;
    ll0.x = __float2bfloat16(v.x - __bfloat162float(h0));
    ll0.y = __float2bfloat16(v.y - __bfloat162float(h1));
    ll1.x = __float2bfloat16(v.z - __bfloat162float(h2));
    ll1.y = __float2bfloat16(v.w - __bfloat162float(h3));
    ((__nv_bfloat162*)hi)[i * 2 + 0] = hh0;
    ((__nv_bfloat162*)hi)[i * 2 + 1] = hh1;
    ((__nv_bfloat162*)lo)[i * 2 + 0] = ll0;
    ((__nv_bfloat162*)lo)[i * 2 + 1] = ll1;
}

#define NQ4 (NLAYER * E3 * EDIM / 4)
#define NP4 (NLAYER * EDIM * EDIM / 4)
#define N14 (NLAYER * E4 * EDIM / 4)

__global__ __launch_bounds__(256) void cvt_all_kernel(
    const float* __restrict__ wq, __nv_bfloat16* __restrict__ wqh,
    __nv_bfloat16* __restrict__ wql,
    const float* __restrict__ wp, __nv_bfloat16* __restrict__ wph,
    __nv_bfloat16* __restrict__ wpl,
    const float* __restrict__ w1, __nv_bfloat16* __restrict__ w1h,
    __nv_bfloat16* __restrict__ w1l,
    const float* __restrict__ w2, __nv_bfloat16* __restrict__ w2h,
    __nv_bfloat16* __restrict__ w2l)
{
    int i = blockIdx.x * 256 + threadIdx.x;
    if (i < NQ4) { cvt4(wq, wqh, wql, i); return; }
    i -= NQ4;
    if (i < NP4) { cvt4(wp, wph, wpl, i); return; }
    i -= NP4;
    if (i < N14) { cvt4(w1, w1h, w1l, i); return; }
    i -= N14;
    if (i < N14) { cvt4(w2, w2h, w2l, i); }
}
#define CVT_TOTAL (NQ4 + NP4 + 2 * N14)

// ---------------------------------------------------------------------------
// Embedding
// ---------------------------------------------------------------------------
__global__ __launch_bounds__(192) void embed_kernel(
    const int* __restrict__ idx, const float* __restrict__ wte,
    const float* __restrict__ wpe, float* __restrict__ x)
{
    const int n = blockIdx.x;
    const int t = n & (TSEQ - 1);
    const int tok = idx[n];
    const float4* pw = (const float4*)(wte + (size_t)tok * EDIM);
    const float4* pp = (const float4*)(wpe + (size_t)t * EDIM);
    float4* po = (float4*)(x + (size_t)n * EDIM);
    const int i = threadIdx.x;
    float4 a = pw[i], b = pp[i];
    po[i] = make_float4(a.x + b.x, a.y + b.y, a.z + b.z, a.w + b.w);
}

// ---------------------------------------------------------------------------
// LayerNorm.  OUTM=0 -> fp32 out; OUTM=1 -> bf16 hi/lo pair
// ---------------------------------------------------------------------------
template<int OUTM>
__global__ __launch_bounds__(256) void ln_kernel(
    const float* __restrict__ x, const float* __restrict__ w,
    const float* __restrict__ b, float* __restrict__ outf,
    __nv_bfloat16* __restrict__ outh, __nv_bfloat16* __restrict__ outl,
    int stride, int offset)
{
    __shared__ float red[8];
    const int row = blockIdx.x * stride + offset;
    const float* px = x + (size_t)row * EDIM;
    const int tid = threadIdx.x;

    float v0 = px[tid], v1 = px[tid + 256], v2 = px[tid + 512];
    float s = v0 + v1 + v2;
    #pragma unroll
    for (int o = 16; o; o >>= 1) s += __shfl_xor_sync(0xffffffffu, s, o);
    if ((tid & 31) == 0) red[tid >> 5] = s;
    __syncthreads();
    float tot = red[0]+red[1]+red[2]+red[3]+red[4]+red[5]+red[6]+red[7];
    const float mu = tot * (1.0f / EDIM);

    float d0 = v0 - mu, d1 = v1 - mu, d2 = v2 - mu;
    float q = d0*d0 + d1*d1 + d2*d2;
    #pragma unroll
    for (int o = 16; o; o >>= 1) q += __shfl_xor_sync(0xffffffffu, q, o);
    __syncthreads();
    if ((tid & 31) == 0) red[tid >> 5] = q;
    __syncthreads();
    float qt = red[0]+red[1]+red[2]+red[3]+red[4]+red[5]+red[6]+red[7];
    const float rstd = rsqrtf(qt * (1.0f / EDIM) + 1e-5f);

    const size_t ob = (size_t)blockIdx.x * EDIM;
    #pragma unroll
    for (int c = 0; c < 3; ++c) {
        const int col = tid + c * 256;
        const float dd = (c == 0 ? d0 : (c == 1 ? d1 : d2));
        float v = dd * rstd * w[col] + b[col];
        if (OUTM == 0) {
            outf[ob + col] = v;
        } else {
            __nv_bfloat16 h = __float2bfloat16(v);
            outh[ob + col] = h;
            outl[ob + col] = __float2bfloat16(v - __bfloat162float(h));
        }
    }
}

// ---------------------------------------------------------------------------
// HMMA GEMM: 256x128 CTA tile, BK=64, 2 stages x 96KB, 512 threads,
// 16 warps (4x4), warp tile 64x32, register fragment double buffer.
// Stage layout: Ah 32K | Al 32K | Bh 16K | Bl 16K.
// MODE: 1 bias+gelu->bf16 hi/lo   2 bias+residual->fp32   3 bias->bf16 hi/lo
// ---------------------------------------------------------------------------
#define STG_BYTES 98304
#define GEMM_SMEM (2 * STG_BYTES)    // 192 KB

__device__ __forceinline__ void g_load_stage(
    uint32_t sbase,
    const __nv_bfloat16* __restrict__ Ah, const __nv_bfloat16* __restrict__ Al,
    const __nv_bfloat16* __restrict__ Bh, const __nv_bfloat16* __restrict__ Bl,
    int K, int k0, int tid)
{
    // A tiles: 256 rows x 8 chunks each (hi then lo)
    #pragma unroll
    for (int half = 0; half < 2; ++half) {
        const __nv_bfloat16* S = half ? Al : Ah;
        const uint32_t base = sbase + half * 32768;
        #pragma unroll
        for (int it = 0; it < 4; ++it) {
            const int i = tid + it * 512;
            const int row = i >> 3, c = i & 7;
            cpa16(base + (row << 7) + ((c ^ (row & 7)) << 4),
                  S + (size_t)row * K + k0 + c * 8);
        }
    }
    // B tiles: 128 rows x 8 chunks each
    #pragma unroll
    for (int half = 0; half < 2; ++half) {
        const __nv_bfloat16* S = half ? Bl : Bh;
        const uint32_t base = sbase + 65536 + half * 16384;
        #pragma unroll
        for (int it = 0; it < 2; ++it) {
            const int i = tid + it * 512;
            const int row = i >> 3, c = i & 7;
            cpa16(base + (row << 7) + ((c ^ (row & 7)) << 4),
                  S + (size_t)row * K + k0 + c * 8);
        }
    }
    cpa_commit();
}

template<int MODE>
__global__ __launch_bounds__(512, 1) void hmma_gemm(
    const __nv_bfloat16* __restrict__ Ah, const __nv_bfloat16* __restrict__ Al,
    const __nv_bfloat16* __restrict__ Bh, const __nv_bfloat16* __restrict__ Bl,
    const float* __restrict__ bias, const float* __restrict__ R,
    float* __restrict__ Cf, __nv_bfloat16* __restrict__ Ch,
    __nv_bfloat16* __restrict__ Cl, int M, int N, int K)
{
    extern __shared__ char smem[];
    const uint32_t sb = smem_u32(smem);
    const int tid = threadIdx.x;
    const int wid = tid >> 5;
    const int lane = tid & 31;
    const int wm = wid >> 2;          // 0..3  (64 rows each)
    const int wn = wid & 3;           // 0..3  (32 cols each)
    const int bm = blockIdx.y * 256;
    const int bn = blockIdx.x * 128;

    const int nkk = K >> 6;

    Ah += (size_t)bm * K; Al += (size_t)bm * K;
    Bh += (size_t)bn * K; Bl += (size_t)bn * K;

    g_load_stage(sb, Ah, Al, Bh, Bl, K, 0, tid);
    g_load_stage(sb + STG_BYTES, Ah, Al, Bh, Bl, K, 64, tid);

    float acc[4][4][4];
    #pragma unroll
    for (int i = 0; i < 4; ++i)
        #pragma unroll
        for (int j = 0; j < 4; ++j)
            #pragma unroll
            for (int q = 0; q < 4; ++q) acc[i][j][q] = 0.0f;

    const int arow = wm * 64 + (lane & 15);
    const int akoff = (lane >> 4);
    const int brow_base = wn * 32 + (lane & 7);
    const int bkoff = ((lane >> 3) & 1);

    uint32_t afh[2][4][4], afl[2][4][4], bfh[2][4][2], bfl[2][4][2];

    for (int kt = 0; kt < nkk; ++kt) {
        cpa_wait<1>();
        __syncthreads();

        const uint32_t sA  = sb + (uint32_t)(kt & 1) * STG_BYTES;
        const uint32_t sAl = sA + 32768;
        const uint32_t sBh = sA + 65536;
        const uint32_t sBl = sA + 81920;

        // preload ks = 0 fragments into buffer 0
        {
            const int kc = akoff;
            #pragma unroll
            for (int mi = 0; mi < 4; ++mi) {
                const int r = arow + mi * 16;
                const uint32_t off = (r << 7) + ((kc ^ (r & 7)) << 4);
                ldsm_x4(afh[0][mi], sA + off);
                ldsm_x4(afl[0][mi], sAl + off);
            }
            const int kcb = bkoff;
            #pragma unroll
            for (int ni = 0; ni < 4; ++ni) {
                const int r = brow_base + ni * 8;
                const uint32_t off = (r << 7) + ((kcb ^ (r & 7)) << 4);
                ldsm_x2(bfh[0][ni], sBh + off);
                ldsm_x2(bfl[0][ni], sBl + off);
            }
        }

        #pragma unroll
        for (int ks = 0; ks < 4; ++ks) {
            const int cur = ks & 1;
            if (ks < 3) {
                const int nxt = cur ^ 1;
                const int kc = (ks + 1) * 2 + akoff;
                #pragma unroll
                for (int mi = 0; mi < 4; ++mi) {
                    const int r = arow + mi * 16;
                    const uint32_t off = (r << 7) + ((kc ^ (r & 7)) << 4);
                    ldsm_x4(afh[nxt][mi], sA + off);
                    ldsm_x4(afl[nxt][mi], sAl + off);
                }
                const int kcb = (ks + 1) * 2 + bkoff;
                #pragma unroll
                for (int ni = 0; ni < 4; ++ni) {
                    const int r = brow_base + ni * 8;
                    const uint32_t off = (r << 7) + ((kcb ^ (r & 7)) << 4);
                    ldsm_x2(bfh[nxt][ni], sBh + off);
                    ldsm_x2(bfl[nxt][ni], sBl + off);
                }
            }
            #pragma unroll
            for (int ni = 0; ni < 4; ++ni)
                #pragma unroll
                for (int mi = 0; mi < 4; ++mi) {
                    mma_bf16(acc[mi][ni], afh[cur][mi], bfh[cur][ni]);
                    mma_bf16(acc[mi][ni], afh[cur][mi], bfl[cur][ni]);
                    mma_bf16(acc[mi][ni], afl[cur][mi], bfh[cur][ni]);
                }
        }

        __syncthreads();    // reads of stage kt complete before overwrite
        if (kt + 2 < nkk) {
            g_load_stage(sA, Ah, Al, Bh, Bl, K, (kt + 2) * 64, tid);
        } else {
            cpa_commit();   // keep group counting uniform
        }
    }

    // epilogue
    const int grp = lane >> 2;
    const int tig = lane & 3;
    #pragma unroll
    for (int mi = 0; mi < 4; ++mi) {
        #pragma unroll
        for (int half = 0; half < 2; ++half) {
            const int grow = bm + wm * 64 + mi * 16 + grp + half * 8;
            #pragma unroll
            for (int ni = 0; ni < 4; ++ni) {
                const int gcol = bn + wn * 32 + ni * 8 + tig * 2;
                float v0 = acc[mi][ni][half * 2 + 0] + bias[gcol];
                float v1 = acc[mi][ni][half * 2 + 1] + bias[gcol + 1];
                if (MODE == 2) {
                    float2 rr = *(const float2*)(R + (size_t)grow * N + gcol);
                    *(float2*)(Cf + (size_t)grow * N + gcol) =
                        make_float2(v0 + rr.x, v1 + rr.y);
                } else {
                    if (MODE == 1) { v0 = gelu_exact(v0); v1 = gelu_exact(v1); }
                    __nv_bfloat16 h0 = __float2bfloat16(v0);
                    __nv_bfloat16 h1 = __float2bfloat16(v1);
                    __nv_bfloat162 hh, ll;
                    hh.x = h0; hh.y = h1;
                    ll.x = __float2bfloat16(v0 - __bfloat162float(h0));
                    ll.y = __float2bfloat16(v1 - __bfloat162float(h1));
                    *(__nv_bfloat162*)(Ch + (size_t)grow * N + gcol) = hh;
                    *(__nv_bfloat162*)(Cl + (size_t)grow * N + gcol) = ll;
                }
            }
        }
    }
}

// ---------------------------------------------------------------------------
// HMMA flash attention (round-4 double-buffered config). Heavy q-tiles first.
// ---------------------------------------------------------------------------
#define ATT_SMEM (16384 + 2 * 32768)

__device__ __forceinline__ void attn_stage_load(
    uint32_t sbase, const __nv_bfloat16* __restrict__ qh,
    const __nv_bfloat16* __restrict__ ql, int growbase, int colbase, int tid)
{
    #pragma unroll
    for (int it = 0; it < 16; ++it) {
        const int i = tid + it * 128;
        const int tile = i >> 9;          // 0 Kh, 1 Kl, 2 Vh, 3 Vl
        const int r = (i >> 3) & 63;
        const int c = i & 7;
        const __nv_bfloat16* arr = (tile & 1) ? ql : qh;
        const int seg = (tile >> 1) ? 2 * EDIM : 0;
        cpa16(sbase + tile * 8192 + (r << 7) + ((c ^ (r & 7)) << 4),
              arr + (size_t)(growbase + r) * E3 + seg + colbase + c * 8);
    }
}

__global__ __launch_bounds__(128, 2) void attn_kernel(
    const __nv_bfloat16* __restrict__ qh, const __nv_bfloat16* __restrict__ ql,
    __nv_bfloat16* __restrict__ yh, __nv_bfloat16* __restrict__ yl)
{
    extern __shared__ char smem[];
    const uint32_t sb = smem_u32(smem);
    const int tid = threadIdx.x;
    const int w = tid >> 5;
    const int lane = tid & 31;
    const int qt = gridDim.x - 1 - blockIdx.x;   // heavy tiles first
    const int bh = blockIdx.y;
    const int b = bh / NHEAD;
    const int hh = bh % NHEAD;
    const int colbase = hh * HDIM;
    const int qrowbase = b * TSEQ + qt * 64;

    #pragma unroll
    for (int it = 0; it < 8; ++it) {
        const int i = tid + it * 128;
        const int tile = i >> 9;
        const int r = (i >> 3) & 63;
        const int c = i & 7;
        const __nv_bfloat16* arr = tile ? ql : qh;
        cpa16(sb + tile * 8192 + (r << 7) + ((c ^ (r & 7)) << 4),
              arr + (size_t)(qrowbase + r) * E3 + EDIM + colbase + c * 8);
    }
    attn_stage_load(sb + 16384, qh, ql, b * TSEQ, colbase, tid);
    cpa_commit();

    uint32_t qfh[4][4], qfl[4][4];
    float o[8][4];
    #pragma unroll
    for (int ni = 0; ni < 8; ++ni)
        #pragma unroll
        for (int q = 0; q < 4; ++q) o[ni][q] = 0.0f;
    float m0 = -1e30f, m1 = -1e30f, l0 = 0.0f, l1 = 0.0f;

    const uint32_t stg[2] = { sb + 16384, sb + 16384 + 32768 };
    const int rl0 = w * 16 + (lane >> 2);
    const int cl0 = (lane & 3) * 2;

    for (int kt = 0; kt <= qt; ++kt) {
        if (kt + 1 <= qt)
            attn_stage_load(stg[(kt + 1) & 1], qh, ql,
                            b * TSEQ + (kt + 1) * 64, colbase, tid);
        cpa_commit();
        cpa_wait<1>();
        __syncthreads();

        if (kt == 0) {
            const int r = w * 16 + (lane & 15);
            #pragma unroll
            for (int ks = 0; ks < 4; ++ks) {
                const int kc = ks * 2 + (lane >> 4);
                const uint32_t off = (r << 7) + ((kc ^ (r & 7)) << 4);
                ldsm_x4(qfh[ks], sb + off);
                ldsm_x4(qfl[ks], sb + 8192 + off);
            }
        }

        const uint32_t sKh = stg[kt & 1];
        const uint32_t sKl = sKh + 8192;
        const uint32_t sVh = sKh + 16384;
        const uint32_t sVl = sKh + 24576;

        float s[8][4];
        #pragma unroll
        for (int ni = 0; ni < 8; ++ni)
            #pragma unroll
            for (int q = 0; q < 4; ++q) s[ni][q] = 0.0f;

        #pragma unroll
        for (int ks = 0; ks < 4; ++ks) {
            const int kcb = ks * 2 + ((lane >> 3) & 1);
            #pragma unroll
            for (int ni = 0; ni < 8; ++ni) {
                const int r = ni * 8 + (lane & 7);
                const uint32_t off = (r << 7) + ((kcb ^ (r & 7)) << 4);
                uint32_t kfh[2], kfl[2];
                ldsm_x2(kfh, sKh + off);
                ldsm_x2(kfl, sKl + off);
                mma_bf16(s[ni], qfh[ks], kfh);
                mma_bf16(s[ni], qfh[ks], kfl);
                mma_bf16(s[ni], qfl[ks], kfh);
            }
        }

        if (kt == qt) {
            #pragma unroll
            for (int ni = 0; ni < 8; ++ni) {
                const int c0 = ni * 8 + cl0;
                if (c0 > rl0)     s[ni][0] = -1e30f;
                if (c0 + 1 > rl0) s[ni][1] = -1e30f;
                if (c0 > rl0 + 8)     s[ni][2] = -1e30f;
                if (c0 + 1 > rl0 + 8) s[ni][3] = -1e30f;
            }
        }

        float mx0 = -1e30f, mx1 = -1e30f;
        #pragma unroll
        for (int ni = 0; ni < 8; ++ni) {
            mx0 = fmaxf(mx0, fmaxf(s[ni][0], s[ni][1]));
            mx1 = fmaxf(mx1, fmaxf(s[ni][2], s[ni][3]));
        }
        mx0 = fmaxf(mx0, __shfl_xor_sync(0xffffffffu, mx0, 1, 4));
        mx0 = fmaxf(mx0, __shfl_xor_sync(0xffffffffu, mx0, 2, 4));
        mx1 = fmaxf(mx1, __shfl_xor_sync(0xffffffffu, mx1, 1, 4));
        mx1 = fmaxf(mx1, __shfl_xor_sync(0xffffffffu, mx1, 2, 4));
        const float nm0 = fmaxf(m0, mx0), nm1 = fmaxf(m1, mx1);
        const float al0 = __expf(m0 - nm0), al1 = __expf(m1 - nm1);
        float rs0 = 0.0f, rs1 = 0.0f;
        #pragma unroll
        for (int ni = 0; ni < 8; ++ni) {
            s[ni][0] = __expf(s[ni][0] - nm0); rs0 += s[ni][0];
            s[ni][1] = __expf(s[ni][1] - nm0); rs0 += s[ni][1];
            s[ni][2] = __expf(s[ni][2] - nm1); rs1 += s[ni][2];
            s[ni][3] = __expf(s[ni][3] - nm1); rs1 += s[ni][3];
        }
        rs0 += __shfl_xor_sync(0xffffffffu, rs0, 1, 4);
        rs0 += __shfl_xor_sync(0xffffffffu, rs0, 2, 4);
        rs1 += __shfl_xor_sync(0xffffffffu, rs1, 1, 4);
        rs1 += __shfl_xor_sync(0xffffffffu, rs1, 2, 4);
        l0 = l0 * al0 + rs0; m0 = nm0;
        l1 = l1 * al1 + rs1; m1 = nm1;
        #pragma unroll
        for (int ni = 0; ni < 8; ++ni) {
            o[ni][0] *= al0; o[ni][1] *= al0;
            o[ni][2] *= al1; o[ni][3] *= al1;
        }

        uint32_t pah[4][4], pal[4][4];
        #pragma unroll
        for (int kc = 0; kc < 4; ++kc) {
            #pragma unroll
            for (int half = 0; half < 2; ++half) {
                const int ni = kc * 2 + half;
                #pragma unroll
                for (int pr = 0; pr < 2; ++pr) {
                    float p0 = s[ni][pr * 2 + 0];
                    float p1 = s[ni][pr * 2 + 1];
                    __nv_bfloat16 h0 = __float2bfloat16(p0);
                    __nv_bfloat16 h1 = __float2bfloat16(p1);
                    __nv_bfloat162 hh, ll;
                    hh.x = h0; hh.y = h1;
                    ll.x = __float2bfloat16(p0 - __bfloat162float(h0));
                    ll.y = __float2bfloat16(p1 - __bfloat162float(h1));
                    pah[kc][half * 2 + pr] = *(uint32_t*)&hh;
                    pal[kc][half * 2 + pr] = *(uint32_t*)&ll;
                }
            }
        }

        #pragma unroll
        for (int kc = 0; kc < 4; ++kc) {
            const int rV = kc * 16 + (lane & 15);
            #pragma unroll
            for (int ni = 0; ni < 8; ++ni) {
                const uint32_t off = (rV << 7) + ((ni ^ (rV & 7)) << 4);
                uint32_t vfh[2], vfl[2];
                ldsm_x2t(vfh, sVh + off);
                ldsm_x2t(vfl, sVl + off);
                mma_bf16(o[ni], pah[kc], vfh);
                mma_bf16(o[ni], pah[kc], vfl);
                mma_bf16(o[ni], pal[kc], vfh);
            }
        }
        __syncthreads();
    }

    const float il0 = 1.0f / l0, il1 = 1.0f / l1;
    const size_t row0 = (size_t)(qrowbase + rl0) * EDIM + colbase + cl0;
    const size_t row1 = (size_t)(qrowbase + rl0 + 8) * EDIM + colbase + cl0;
    #pragma unroll
    for (int ni = 0; ni < 8; ++ni) {
        const int dc = ni * 8;
        float v0 = o[ni][0] * il0, v1 = o[ni][1] * il0;
        float v2 = o[ni][2] * il1, v3 = o[ni][3] * il1;
        __nv_bfloat16 h0 = __float2bfloat16(v0), h1 = __float2bfloat16(v1);
        __nv_bfloat16 h2 = __float2bfloat16(v2), h3 = __float2bfloat16(v3);
        __nv_bfloat162 a, bb, c, d;
        a.x = h0; a.y = h1; c.x = h2; c.y = h3;
        bb.x = __float2bfloat16(v0 - __bfloat162float(h0));
        bb.y = __float2bfloat16(v1 - __bfloat162float(h1));
        d.x = __float2bfloat16(v2 - __bfloat162float(h2));
        d.y = __float2bfloat16(v3 - __bfloat162float(h3));
        *(__nv_bfloat162*)(yh + row0 + dc) = a;
        *(__nv_bfloat162*)(yl + row0 + dc) = bb;
        *(__nv_bfloat162*)(yh + row1 + dc) = c;
        *(__nv_bfloat162*)(yl + row1 + dc) = d;
    }
}

// ---------------------------------------------------------------------------
// lm_head
// ---------------------------------------------------------------------------
__global__ __launch_bounds__(256) void logits_kernel(
    const float* __restrict__ xf, const float* __restrict__ wte,
    const float* __restrict__ lm_b, float* __restrict__ out)
{
    __shared__ float xs[NBATCH * EDIM];
    for (int i = threadIdx.x; i < NBATCH * EDIM; i += 256) xs[i] = xf[i];
    __syncthreads();

    const int warp = threadIdx.x >> 5;
    const int lane = threadIdx.x & 31;
    const int v = blockIdx.x * 8 + warp;

    const float* wrow = wte + (size_t)v * EDIM;
    float acc[NBATCH];
    #pragma unroll
    for (int b = 0; b < NBATCH; ++b) acc[b] = 0.0f;

    for (int k4 = lane * 4; k4 < EDIM; k4 += 128) {
        float4 wv = *(const float4*)(wrow + k4);
        #pragma unroll
        for (int b = 0; b < NBATCH; ++b) {
            float4 xv = *(const float4*)(xs + b * EDIM + k4);
            acc[b] += wv.x*xv.x + wv.y*xv.y + wv.z*xv.z + wv.w*xv.w;
        }
    }
    #pragma unroll
    for (int o = 16; o; o >>= 1)
        #pragma unroll
        for (int b = 0; b < NBATCH; ++b)
            acc[b] += __shfl_xor_sync(0xffffffffu, acc[b], o);

    if (lane == 0) {
        const float bb = lm_b[v];
        #pragma unroll
        for (int b = 0; b < NBATCH; ++b)
            out[(size_t)b * VOCAB + v] = acc[b] + bb;
    }
}

// ---------------------------------------------------------------------------
// Launcher
// ---------------------------------------------------------------------------
extern "C" void kernel_launch(void* const* d_in, const int* in_sizes, int n_in,
                              void* d_out, int out_size)
{
    (void)in_sizes; (void)n_in; (void)out_size;
    const int*   idx    = (const int*)  d_in[0];
    const float* wte    = (const float*)d_in[1];
    const float* wpe    = (const float*)d_in[2];
    const float* qkv_w  = (const float*)d_in[3];
    const float* qkv_b  = (const float*)d_in[4];
    const float* proj_w = (const float*)d_in[5];
    const float* proj_b = (const float*)d_in[6];
    const float* ln_w   = (const float*)d_in[7];
    const float* ln_b   = (const float*)d_in[8];
    const float* c1_w   = (const float*)d_in[9];
    const float* c1_b   = (const float*)d_in[10];
    const float* c2_w   = (const float*)d_in[11];
    const float* c2_b   = (const float*)d_in[12];
    const float* lnf_w  = (const float*)d_in[13];
    const float* lnf_b  = (const float*)d_in[14];
    const float* lm_b   = (const float*)d_in[15];
    float* out = (float*)d_out;

    float *x, *xf;
    __nv_bfloat16 *h_hi, *h_lo, *qv_h, *qv_l, *att_hi, *att_lo, *a1_hi, *a1_lo;
    __nv_bfloat16 *wq_h, *wq_l, *wp_h, *wp_l, *w1_h, *w1_l, *w2_h, *w2_l;
    cudaGetSymbolAddress((void**)&x,     g_x);
    cudaGetSymbolAddress((void**)&xf,    g_xf);
    cudaGetSymbolAddress((void**)&h_hi,  g_h_hi);
    cudaGetSymbolAddress((void**)&h_lo,  g_h_lo);
    cudaGetSymbolAddress((void**)&qv_h,  g_qkv_hi);
    cudaGetSymbolAddress((void**)&qv_l,  g_qkv_lo);
    cudaGetSymbolAddress((void**)&att_hi,g_att_hi);
    cudaGetSymbolAddress((void**)&att_lo,g_att_lo);
    cudaGetSymbolAddress((void**)&a1_hi, g_a1_hi);
    cudaGetSymbolAddress((void**)&a1_lo, g_a1_lo);
    cudaGetSymbolAddress((void**)&wq_h,  g_wqkv_hi);
    cudaGetSymbolAddress((void**)&wq_l,  g_wqkv_lo);
    cudaGetSymbolAddress((void**)&wp_h,  g_wprj_hi);
    cudaGetSymbolAddress((void**)&wp_l,  g_wprj_lo);
    cudaGetSymbolAddress((void**)&w1_h,  g_wc1_hi);
    cudaGetSymbolAddress((void**)&w1_l,  g_wc1_lo);
    cudaGetSymbolAddress((void**)&w2_h,  g_wc2_hi);
    cudaGetSymbolAddress((void**)&w2_l,  g_wc2_lo);

    cudaFuncSetAttribute(attn_kernel,
        cudaFuncAttributeMaxDynamicSharedMemorySize, ATT_SMEM);
    cudaFuncSetAttribute(hmma_gemm<1>,
        cudaFuncAttributeMaxDynamicSharedMemorySize, GEMM_SMEM);
    cudaFuncSetAttribute(hmma_gemm<2>,
        cudaFuncAttributeMaxDynamicSharedMemorySize, GEMM_SMEM);
    cudaFuncSetAttribute(hmma_gemm<3>,
        cudaFuncAttributeMaxDynamicSharedMemorySize, GEMM_SMEM);

    cvt_all_kernel<<<(CVT_TOTAL + 255) / 256, 256>>>(
        qkv_w, wq_h, wq_l, proj_w, wp_h, wp_l,
        c1_w, w1_h, w1_l, c2_w, w2_h, w2_l);

    embed_kernel<<<NTOK, 192>>>(idx, wte, wpe, x);

    for (int l = 0; l < NLAYER; ++l) {
        const float* lw = ln_w + l * EDIM;
        const float* lb = ln_b + l * EDIM;
        const size_t oq = (size_t)l * E3 * EDIM;
        const size_t op = (size_t)l * EDIM * EDIM;
        const size_t o1 = (size_t)l * E4 * EDIM;

        ln_kernel<1><<<NTOK, 256>>>(x, lw, lb, nullptr, h_hi, h_lo, 1, 0);
        hmma_gemm<3><<<dim3(E3 / 128, NTOK / 256), 512, GEMM_SMEM>>>(
            h_hi, h_lo, wq_h + oq, wq_l + oq, qkv_b + (size_t)l * E3,
            nullptr, nullptr, qv_h, qv_l, NTOK, E3, EDIM);
        attn_kernel<<<dim3(TSEQ / 64, NBATCH * NHEAD), 128, ATT_SMEM>>>(
            qv_h, qv_l, att_hi, att_lo);
        hmma_gemm<2><<<dim3(EDIM / 128, NTOK / 256), 512, GEMM_SMEM>>>(
            att_hi, att_lo, wp_h + op, wp_l + op, proj_b + (size_t)l * EDIM,
            x, x, nullptr, nullptr, NTOK, EDIM, EDIM);

        ln_kernel<1><<<NTOK, 256>>>(x, lw, lb, nullptr, h_hi, h_lo, 1, 0);
        hmma_gemm<1><<<dim3(E4 / 128, NTOK / 256), 512, GEMM_SMEM>>>(
            h_hi, h_lo, w1_h + o1, w1_l + o1, c1_b + (size_t)l * E4,
            nullptr, nullptr, a1_hi, a1_lo, NTOK, E4, EDIM);
        hmma_gemm<2><<<dim3(EDIM / 128, NTOK / 256), 512, GEMM_SMEM>>>(
            a1_hi, a1_lo, w2_h + o1, w2_l + o1, c2_b + (size_t)l * EDIM,
            x, x, nullptr, nullptr, NTOK, EDIM, E4);
    }

    ln_kernel<0><<<NBATCH, 256>>>(x, lnf_w, lnf_b, xf, nullptr, nullptr,
                                  TSEQ, TSEQ - 1);
    logits_kernel<<<VOCAB / 8, 256>>>(xf, wte, lm_b, out);
}

// round 12
// speedup vs baseline: 1.0204x; 1.0204x over previous
#include <cuda_runtime.h>
#include <cuda_bf16.h>
#include <math.h>
#include <stdint.h>

// ---------------------------------------------------------------------------
// GPT-2 small forward: B=8, T=1024, E=768, H=12, D=64, L=12, V=50304
// Round 12: GEMM 128x256 CTA / 8 warps / 64x64 warp tile (96 MMA : 16 ldsm
// per k16 step -> raise tensor-pipe duty). B fragments via ldsm_x4 (2 n-tiles).
// Attention = round-4 proven config. Fused cvt.
// ---------------------------------------------------------------------------

#define NTOK   8192
#define EDIM   768
#define E3     2304
#define E4     3072
#define NHEAD  12
#define HDIM   64
#define NLAYER 12
#define VOCAB  50304
#define NBATCH 8
#define TSEQ   1024

// ---------------- device scratch (allocation-free) ----------------
__device__ __align__(16) float          g_x    [NTOK * EDIM];
__device__ __align__(16) float          g_xf   [NBATCH * EDIM];
__device__ __align__(16) __nv_bfloat16  g_h_hi  [NTOK * EDIM];
__device__ __align__(16) __nv_bfloat16  g_h_lo  [NTOK * EDIM];
__device__ __align__(16) __nv_bfloat16  g_qkv_hi[NTOK * E3];
__device__ __align__(16) __nv_bfloat16  g_qkv_lo[NTOK * E3];
__device__ __align__(16) __nv_bfloat16  g_att_hi[NTOK * EDIM];
__device__ __align__(16) __nv_bfloat16  g_att_lo[NTOK * EDIM];
__device__ __align__(16) __nv_bfloat16  g_a1_hi [NTOK * E4];
__device__ __align__(16) __nv_bfloat16  g_a1_lo [NTOK * E4];
__device__ __align__(16) __nv_bfloat16  g_wqkv_hi[NLAYER * E3 * EDIM];
__device__ __align__(16) __nv_bfloat16  g_wqkv_lo[NLAYER * E3 * EDIM];
__device__ __align__(16) __nv_bfloat16  g_wprj_hi[NLAYER * EDIM * EDIM];
__device__ __align__(16) __nv_bfloat16  g_wprj_lo[NLAYER * EDIM * EDIM];
__device__ __align__(16) __nv_bfloat16  g_wc1_hi [NLAYER * E4 * EDIM];
__device__ __align__(16) __nv_bfloat16  g_wc1_lo [NLAYER * E4 * EDIM];
__device__ __align__(16) __nv_bfloat16  g_wc2_hi [NLAYER * EDIM * E4];
__device__ __align__(16) __nv_bfloat16  g_wc2_lo [NLAYER * EDIM * E4];

// ---------------- helpers ----------------
__device__ __forceinline__ uint32_t smem_u32(const void* p) {
    uint32_t a;
    asm("{ .reg .u64 t; cvta.to.shared.u64 t, %1; cvt.u32.u64 %0, t; }"
        : "=r"(a) : "l"(p));
    return a;
}
__device__ __forceinline__ void cpa16(uint32_t dst, const void* src) {
    asm volatile("cp.async.cg.shared.global [%0], [%1], 16;" :: "r"(dst), "l"(src));
}
__device__ __forceinline__ void cpa_commit() {
    asm volatile("cp.async.commit_group;" ::: "memory");
}
template<int N> __device__ __forceinline__ void cpa_wait() {
    asm volatile("cp.async.wait_group %0;" :: "n"(N) : "memory");
}
__device__ __forceinline__ void ldsm_x4(uint32_t* r, uint32_t a) {
    asm volatile("ldmatrix.sync.aligned.m8n8.x4.shared.b16 {%0,%1,%2,%3}, [%4];"
        : "=r"(r[0]), "=r"(r[1]), "=r"(r[2]), "=r"(r[3]) : "r"(a));
}
__device__ __forceinline__ void ldsm_x4p(uint32_t* r0, uint32_t* r1, uint32_t a) {
    asm volatile("ldmatrix.sync.aligned.m8n8.x4.shared.b16 {%0,%1,%2,%3}, [%4];"
        : "=r"(r0[0]), "=r"(r0[1]), "=r"(r1[0]), "=r"(r1[1]) : "r"(a));
}
__device__ __forceinline__ void ldsm_x2(uint32_t* r, uint32_t a) {
    asm volatile("ldmatrix.sync.aligned.m8n8.x2.shared.b16 {%0,%1}, [%2];"
        : "=r"(r[0]), "=r"(r[1]) : "r"(a));
}
__device__ __forceinline__ void ldsm_x2t(uint32_t* r, uint32_t a) {
    asm volatile("ldmatrix.sync.aligned.m8n8.x2.trans.shared.b16 {%0,%1}, [%2];"
        : "=r"(r[0]), "=r"(r[1]) : "r"(a));
}
__device__ __forceinline__ void mma_bf16(float* c, const uint32_t* a,
                                         const uint32_t* b) {
    asm volatile(
        "mma.sync.aligned.m16n8k16.row.col.f32.bf16.bf16.f32 "
        "{%0,%1,%2,%3}, {%4,%5,%6,%7}, {%8,%9}, {%0,%1,%2,%3};"
        : "+f"(c[0]), "+f"(c[1]), "+f"(c[2]), "+f"(c[3])
        : "r"(a[0]), "r"(a[1]), "r"(a[2]), "r"(a[3]), "r"(b[0]), "r"(b[1]));
}
__device__ __forceinline__ float gelu_exact(float v) {
    return 0.5f * v * (1.0f + erff(v * 0.70710678118654752f));
}

// ---------------------------------------------------------------------------
// Fused weight convert: all four weight groups in ONE launch.
// ---------------------------------------------------------------------------
__device__ __forceinline__ void cvt4(const float* w, __nv_bfloat16* hi,
                                     __nv_bfloat16* lo, int i) {
    float4 v = ((const float4*)w)[i];
    __nv_bfloat16 h0 = __float2bfloat16(v.x), h1 = __float2bfloat16(v.y);
    __nv_bfloat16 h2 = __float2bfloat16(v.z), h3 = __float2bfloat16(v.w);
    __nv_bfloat162 hh0, hh1, ll0, ll1;
    hh0.x = h0; hh0.y = h1; hh1.x = h2; hh1.y = h3;
    ll0.x = __float2bfloat16(v.x - __bfloat162float(h0));
    ll0.y = __float2bfloat16(v.y - __bfloat162float(h1));
    ll1.x = __float2bfloat16(v.z - __bfloat162float(h2));
    ll1.y = __float2bfloat16(v.w - __bfloat162float(h3));
    ((__nv_bfloat162*)hi)[i * 2 + 0] = hh0;
    ((__nv_bfloat162*)hi)[i * 2 + 1] = hh1;
    ((__nv_bfloat162*)lo)[i * 2 + 0] = ll0;
    ((__nv_bfloat162*)lo)[i * 2 + 1] = ll1;
}

#define NQ4 (NLAYER * E3 * EDIM / 4)
#define NP4 (NLAYER * EDIM * EDIM / 4)
#define N14 (NLAYER * E4 * EDIM / 4)

__global__ __launch_bounds__(256) void cvt_all_kernel(
    const float* __restrict__ wq, __nv_bfloat16* __restrict__ wqh,
    __nv_bfloat16* __restrict__ wql,
    const float* __restrict__ wp, __nv_bfloat16* __restrict__ wph,
    __nv_bfloat16* __restrict__ wpl,
    const float* __restrict__ w1, __nv_bfloat16* __restrict__ w1h,
    __nv_bfloat16* __restrict__ w1l,
    const float* __restrict__ w2, __nv_bfloat16* __restrict__ w2h,
    __nv_bfloat16* __restrict__ w2l)
{
    int i = blockIdx.x * 256 + threadIdx.x;
    if (i < NQ4) { cvt4(wq, wqh, wql, i); return; }
    i -= NQ4;
    if (i < NP4) { cvt4(wp, wph, wpl, i); return; }
    i -= NP4;
    if (i < N14) { cvt4(w1, w1h, w1l, i); return; }
    i -= N14;
    if (i < N14) { cvt4(w2, w2h, w2l, i); }
}
#define CVT_TOTAL (NQ4 + NP4 + 2 * N14)

// ---------------------------------------------------------------------------
// Embedding
// ---------------------------------------------------------------------------
__global__ __launch_bounds__(192) void embed_kernel(
    const int* __restrict__ idx, const float* __restrict__ wte,
    const float* __restrict__ wpe, float* __restrict__ x)
{
    const int n = blockIdx.x;
    const int t = n & (TSEQ - 1);
    const int tok = idx[n];
    const float4* pw = (const float4*)(wte + (size_t)tok * EDIM);
    const float4* pp = (const float4*)(wpe + (size_t)t * EDIM);
    float4* po = (float4*)(x + (size_t)n * EDIM);
    const int i = threadIdx.x;
    float4 a = pw[i], b = pp[i];
    po[i] = make_float4(a.x + b.x, a.y + b.y, a.z + b.z, a.w + b.w);
}

// ---------------------------------------------------------------------------
// LayerNorm.  OUTM=0 -> fp32 out; OUTM=1 -> bf16 hi/lo pair
// ---------------------------------------------------------------------------
template<int OUTM>
__global__ __launch_bounds__(256) void ln_kernel(
    const float* __restrict__ x, const float* __restrict__ w,
    const float* __restrict__ b, float* __restrict__ outf,
    __nv_bfloat16* __restrict__ outh, __nv_bfloat16* __restrict__ outl,
    int stride, int offset)
{
    __shared__ float red[8];
    const int row = blockIdx.x * stride + offset;
    const float* px = x + (size_t)row * EDIM;
    const int tid = threadIdx.x;

    float v0 = px[tid], v1 = px[tid + 256], v2 = px[tid + 512];
    float s = v0 + v1 + v2;
    #pragma unroll
    for (int o = 16; o; o >>= 1) s += __shfl_xor_sync(0xffffffffu, s, o);
    if ((tid & 31) == 0) red[tid >> 5] = s;
    __syncthreads();
    float tot = red[0]+red[1]+red[2]+red[3]+red[4]+red[5]+red[6]+red[7];
    const float mu = tot * (1.0f / EDIM);

    float d0 = v0 - mu, d1 = v1 - mu, d2 = v2 - mu;
    float q = d0*d0 + d1*d1 + d2*d2;
    #pragma unroll
    for (int o = 16; o; o >>= 1) q += __shfl_xor_sync(0xffffffffu, q, o);
    __syncthreads();
    if ((tid & 31) == 0) red[tid >> 5] = q;
    __syncthreads();
    float qt = red[0]+red[1]+red[2]+red[3]+red[4]+red[5]+red[6]+red[7];
    const float rstd = rsqrtf(qt * (1.0f / EDIM) + 1e-5f);

    const size_t ob = (size_t)blockIdx.x * EDIM;
    #pragma unroll
    for (int c = 0; c < 3; ++c) {
        const int col = tid + c * 256;
        const float dd = (c == 0 ? d0 : (c == 1 ? d1 : d2));
        float v = dd * rstd * w[col] + b[col];
        if (OUTM == 0) {
            outf[ob + col] = v;
        } else {
            __nv_bfloat16 h = __float2bfloat16(v);
            outh[ob + col] = h;
            outl[ob + col] = __float2bfloat16(v - __bfloat162float(h));
        }
    }
}

// ---------------------------------------------------------------------------
// HMMA GEMM: 128x256 CTA tile, BK=64, 2 stages x 96KB, 256 threads / 8 warps
// (2x4), warp tile 64x64 -> 96 MMAs : 16 ldsm per k16 step.
// Stage layout: Ah 16K | Al 16K | Bh 32K | Bl 32K.
// MODE: 1 bias+gelu->bf16 hi/lo   2 bias+residual->fp32   3 bias->bf16 hi/lo
// ---------------------------------------------------------------------------
#define STG_BYTES 98304
#define GEMM_SMEM (2 * STG_BYTES)    // 192 KB

__device__ __forceinline__ void g_load_stage(
    uint32_t sbase,
    const __nv_bfloat16* __restrict__ Ah, const __nv_bfloat16* __restrict__ Al,
    const __nv_bfloat16* __restrict__ Bh, const __nv_bfloat16* __restrict__ Bl,
    int K, int k0, int tid)
{
    // A: 128 rows x 8 chunks each (hi, lo)
    #pragma unroll
    for (int half = 0; half < 2; ++half) {
        const __nv_bfloat16* S = half ? Al : Ah;
        const uint32_t base = sbase + half * 16384;
        #pragma unroll
        for (int it = 0; it < 4; ++it) {
            const int i = tid + it * 256;
            const int row = i >> 3, c = i & 7;
            cpa16(base + (row << 7) + ((c ^ (row & 7)) << 4),
                  S + (size_t)row * K + k0 + c * 8);
        }
    }
    // B: 256 rows x 8 chunks each (hi, lo)
    #pragma unroll
    for (int half = 0; half < 2; ++half) {
        const __nv_bfloat16* S = half ? Bl : Bh;
        const uint32_t base = sbase + 32768 + half * 32768;
        #pragma unroll
        for (int it = 0; it < 8; ++it) {
            const int i = tid + it * 256;
            const int row = i >> 3, c = i & 7;
            cpa16(base + (row << 7) + ((c ^ (row & 7)) << 4),
                  S + (size_t)row * K + k0 + c * 8);
        }
    }
    cpa_commit();
}

template<int MODE>
__global__ __launch_bounds__(256) void hmma_gemm(
    const __nv_bfloat16* __restrict__ Ah, const __nv_bfloat16* __restrict__ Al,
    const __nv_bfloat16* __restrict__ Bh, const __nv_bfloat16* __restrict__ Bl,
    const float* __restrict__ bias, const float* __restrict__ R,
    float* __restrict__ Cf, __nv_bfloat16* __restrict__ Ch,
    __nv_bfloat16* __restrict__ Cl, int M, int N, int K)
{
    extern __shared__ char smem[];
    const uint32_t sb = smem_u32(smem);
    const int tid = threadIdx.x;
    const int wid = tid >> 5;
    const int lane = tid & 31;
    const int wm = wid >> 2;          // 0..1  (64 rows)
    const int wn = wid & 3;           // 0..3  (64 cols)
    const int bm = blockIdx.y * 128;
    const int bn = blockIdx.x * 256;

    const int nkk = K >> 6;

    Ah += (size_t)bm * K; Al += (size_t)bm * K;
    Bh += (size_t)bn * K; Bl += (size_t)bn * K;

    g_load_stage(sb, Ah, Al, Bh, Bl, K, 0, tid);
    g_load_stage(sb + STG_BYTES, Ah, Al, Bh, Bl, K, 64, tid);

    float acc[4][8][4];
    #pragma unroll
    for (int i = 0; i < 4; ++i)
        #pragma unroll
        for (int j = 0; j < 8; ++j)
            #pragma unroll
            for (int q = 0; q < 4; ++q) acc[i][j][q] = 0.0f;

    // A fragment addressing (ldsm x4, m16 x k16): lanes 0-15 rows, lane>>4 chunk
    const int arow = wm * 64 + (lane & 15);
    const int akoff = (lane >> 4);
    // B fragment addressing (ldsm x4 over TWO n8 tiles):
    // lanes 0-7: n0-7/kc, 8-15: n0-7/kc+1, 16-23: n8-15/kc, 24-31: n8-15/kc+1
    const int brow = wn * 64 + (lane & 7) + ((lane >> 4) << 3);
    const int bkoff = ((lane >> 3) & 1);

    for (int kt = 0; kt < nkk; ++kt) {
        cpa_wait<1>();
        __syncthreads();

        const uint32_t sA  = sb + (uint32_t)(kt & 1) * STG_BYTES;
        const uint32_t sAl = sA + 16384;
        const uint32_t sBh = sA + 32768;
        const uint32_t sBl = sA + 65536;

        #pragma unroll
        for (int ks = 0; ks < 4; ++ks) {
            uint32_t afh[4][4], afl[4][4], bfh[8][2], bfl[8][2];
            const int kc = ks * 2 + akoff;
            #pragma unroll
            for (int mi = 0; mi < 4; ++mi) {
                const int r = arow + mi * 16;
                const uint32_t off = (r << 7) + ((kc ^ (r & 7)) << 4);
                ldsm_x4(afh[mi], sA + off);
                ldsm_x4(afl[mi], sAl + off);
            }
            const int kcb = ks * 2 + bkoff;
            #pragma unroll
            for (int p = 0; p < 4; ++p) {          // 4 pairs of n8 tiles
                const int r = brow + p * 16;
                const uint32_t off = (r << 7) + ((kcb ^ (r & 7)) << 4);
                ldsm_x4p(bfh[p * 2], bfh[p * 2 + 1], sBh + off);
                ldsm_x4p(bfl[p * 2], bfl[p * 2 + 1], sBl + off);
            }
            #pragma unroll
            for (int ni = 0; ni < 8; ++ni)
                #pragma unroll
                for (int mi = 0; mi < 4; ++mi) {
                    mma_bf16(acc[mi][ni], afh[mi], bfh[ni]);
                    mma_bf16(acc[mi][ni], afh[mi], bfl[ni]);
                    mma_bf16(acc[mi][ni], afl[mi], bfh[ni]);
                }
        }

        __syncthreads();
        if (kt + 2 < nkk) {
            g_load_stage(sA, Ah, Al, Bh, Bl, K, (kt + 2) * 64, tid);
        } else {
            cpa_commit();
        }
    }

    // epilogue
    const int grp = lane >> 2;
    const int tig = lane & 3;
    #pragma unroll
    for (int mi = 0; mi < 4; ++mi) {
        #pragma unroll
        for (int half = 0; half < 2; ++half) {
            const int grow = bm + wm * 64 + mi * 16 + grp + half * 8;
            #pragma unroll
            for (int ni = 0; ni < 8; ++ni) {
                const int gcol = bn + wn * 64 + ni * 8 + tig * 2;
                float v0 = acc[mi][ni][half * 2 + 0] + bias[gcol];
                float v1 = acc[mi][ni][half * 2 + 1] + bias[gcol + 1];
                if (MODE == 2) {
                    float2 rr = *(const float2*)(R + (size_t)grow * N + gcol);
                    *(float2*)(Cf + (size_t)grow * N + gcol) =
                        make_float2(v0 + rr.x, v1 + rr.y);
                } else {
                    if (MODE == 1) { v0 = gelu_exact(v0); v1 = gelu_exact(v1); }
                    __nv_bfloat16 h0 = __float2bfloat16(v0);
                    __nv_bfloat16 h1 = __float2bfloat16(v1);
                    __nv_bfloat162 hh, ll;
                    hh.x = h0; hh.y = h1;
                    ll.x = __float2bfloat16(v0 - __bfloat162float(h0));
                    ll.y = __float2bfloat16(v1 - __bfloat162float(h1));
                    *(__nv_bfloat162*)(Ch + (size_t)grow * N + gcol) = hh;
                    *(__nv_bfloat162*)(Cl + (size_t)grow * N + gcol) = ll;
                }
            }
        }
    }
}

// ---------------------------------------------------------------------------
// HMMA flash attention (round-4 double-buffered config). Heavy q-tiles first.
// ---------------------------------------------------------------------------
#define ATT_SMEM (16384 + 2 * 32768)

__device__ __forceinline__ void attn_stage_load(
    uint32_t sbase, const __nv_bfloat16* __restrict__ qh,
    const __nv_bfloat16* __restrict__ ql, int growbase, int colbase, int tid)
{
    #pragma unroll
    for (int it = 0; it < 16; ++it) {
        const int i = tid + it * 128;
        const int tile = i >> 9;          // 0 Kh, 1 Kl, 2 Vh, 3 Vl
        const int r = (i >> 3) & 63;
        const int c = i & 7;
        const __nv_bfloat16* arr = (tile & 1) ? ql : qh;
        const int seg = (tile >> 1) ? 2 * EDIM : 0;
        cpa16(sbase + tile * 8192 + (r << 7) + ((c ^ (r & 7)) << 4),
              arr + (size_t)(growbase + r) * E3 + seg + colbase + c * 8);
    }
}

__global__ __launch_bounds__(128, 2) void attn_kernel(
    const __nv_bfloat16* __restrict__ qh, const __nv_bfloat16* __restrict__ ql,
    __nv_bfloat16* __restrict__ yh, __nv_bfloat16* __restrict__ yl)
{
    extern __shared__ char smem[];
    const uint32_t sb = smem_u32(smem);
    const int tid = threadIdx.x;
    const int w = tid >> 5;
    const int lane = tid & 31;
    const int qt = gridDim.x - 1 - blockIdx.x;   // heavy tiles first
    const int bh = blockIdx.y;
    const int b = bh / NHEAD;
    const int hh = bh % NHEAD;
    const int colbase = hh * HDIM;
    const int qrowbase = b * TSEQ + qt * 64;

    #pragma unroll
    for (int it = 0; it < 8; ++it) {
        const int i = tid + it * 128;
        const int tile = i >> 9;
        const int r = (i >> 3) & 63;
        const int c = i & 7;
        const __nv_bfloat16* arr = tile ? ql : qh;
        cpa16(sb + tile * 8192 + (r << 7) + ((c ^ (r & 7)) << 4),
              arr + (size_t)(qrowbase + r) * E3 + EDIM + colbase + c * 8);
    }
    attn_stage_load(sb + 16384, qh, ql, b * TSEQ, colbase, tid);
    cpa_commit();

    uint32_t qfh[4][4], qfl[4][4];
    float o[8][4];
    #pragma unroll
    for (int ni = 0; ni < 8; ++ni)
        #pragma unroll
        for (int q = 0; q < 4; ++q) o[ni][q] = 0.0f;
    float m0 = -1e30f, m1 = -1e30f, l0 = 0.0f, l1 = 0.0f;

    const uint32_t stg[2] = { sb + 16384, sb + 16384 + 32768 };
    const int rl0 = w * 16 + (lane >> 2);
    const int cl0 = (lane & 3) * 2;

    for (int kt = 0; kt <= qt; ++kt) {
        if (kt + 1 <= qt)
            attn_stage_load(stg[(kt + 1) & 1], qh, ql,
                            b * TSEQ + (kt + 1) * 64, colbase, tid);
        cpa_commit();
        cpa_wait<1>();
        __syncthreads();

        if (kt == 0) {
            const int r = w * 16 + (lane & 15);
            #pragma unroll
            for (int ks = 0; ks < 4; ++ks) {
                const int kc = ks * 2 + (lane >> 4);
                const uint32_t off = (r << 7) + ((kc ^ (r & 7)) << 4);
                ldsm_x4(qfh[ks], sb + off);
                ldsm_x4(qfl[ks], sb + 8192 + off);
            }
        }

        const uint32_t sKh = stg[kt & 1];
        const uint32_t sKl = sKh + 8192;
        const uint32_t sVh = sKh + 16384;
        const uint32_t sVl = sKh + 24576;

        float s[8][4];
        #pragma unroll
        for (int ni = 0; ni < 8; ++ni)
            #pragma unroll
            for (int q = 0; q < 4; ++q) s[ni][q] = 0.0f;

        #pragma unroll
        for (int ks = 0; ks < 4; ++ks) {
            const int kcb = ks * 2 + ((lane >> 3) & 1);
            #pragma unroll
            for (int ni = 0; ni < 8; ++ni) {
                const int r = ni * 8 + (lane & 7);
                const uint32_t off = (r << 7) + ((kcb ^ (r & 7)) << 4);
                uint32_t kfh[2], kfl[2];
                ldsm_x2(kfh, sKh + off);
                ldsm_x2(kfl, sKl + off);
                mma_bf16(s[ni], qfh[ks], kfh);
                mma_bf16(s[ni], qfh[ks], kfl);
                mma_bf16(s[ni], qfl[ks], kfh);
            }
        }

        if (kt == qt) {
            #pragma unroll
            for (int ni = 0; ni < 8; ++ni) {
                const int c0 = ni * 8 + cl0;
                if (c0 > rl0)     s[ni][0] = -1e30f;
                if (c0 + 1 > rl0) s[ni][1] = -1e30f;
                if (c0 > rl0 + 8)     s[ni][2] = -1e30f;
                if (c0 + 1 > rl0 + 8) s[ni][3] = -1e30f;
            }
        }

        float mx0 = -1e30f, mx1 = -1e30f;
        #pragma unroll
        for (int ni = 0; ni < 8; ++ni) {
            mx0 = fmaxf(mx0, fmaxf(s[ni][0], s[ni][1]));
            mx1 = fmaxf(mx1, fmaxf(s[ni][2], s[ni][3]));
        }
        mx0 = fmaxf(mx0, __shfl_xor_sync(0xffffffffu, mx0, 1, 4));
        mx0 = fmaxf(mx0, __shfl_xor_sync(0xffffffffu, mx0, 2, 4));
        mx1 = fmaxf(mx1, __shfl_xor_sync(0xffffffffu, mx1, 1, 4));
        mx1 = fmaxf(mx1, __shfl_xor_sync(0xffffffffu, mx1, 2, 4));
        const float nm0 = fmaxf(m0, mx0), nm1 = fmaxf(m1, mx1);
        const float al0 = __expf(m0 - nm0), al1 = __expf(m1 - nm1);
        float rs0 = 0.0f, rs1 = 0.0f;
        #pragma unroll
        for (int ni = 0; ni < 8; ++ni) {
            s[ni][0] = __expf(s[ni][0] - nm0); rs0 += s[ni][0];
            s[ni][1] = __expf(s[ni][1] - nm0); rs0 += s[ni][1];
            s[ni][2] = __expf(s[ni][2] - nm1); rs1 += s[ni][2];
            s[ni][3] = __expf(s[ni][3] - nm1); rs1 += s[ni][3];
        }
        rs0 += __shfl_xor_sync(0xffffffffu, rs0, 1, 4);
        rs0 += __shfl_xor_sync(0xffffffffu, rs0, 2, 4);
        rs1 += __shfl_xor_sync(0xffffffffu, rs1, 1, 4);
        rs1 += __shfl_xor_sync(0xffffffffu, rs1, 2, 4);
        l0 = l0 * al0 + rs0; m0 = nm0;
        l1 = l1 * al1 + rs1; m1 = nm1;
        #pragma unroll
        for (int ni = 0; ni < 8; ++ni) {
            o[ni][0] *= al0; o[ni][1] *= al0;
            o[ni][2] *= al1; o[ni][3] *= al1;
        }

        uint32_t pah[4][4], pal[4][4];
        #pragma unroll
        for (int kc = 0; kc < 4; ++kc) {
            #pragma unroll
            for (int half = 0; half < 2; ++half) {
                const int ni = kc * 2 + half;
                #pragma unroll
                for (int pr = 0; pr < 2; ++pr) {
                    float p0 = s[ni][pr * 2 + 0];
                    float p1 = s[ni][pr * 2 + 1];
                    __nv_bfloat16 h0 = __float2bfloat16(p0);
                    __nv_bfloat16 h1 = __float2bfloat16(p1);
                    __nv_bfloat162 hh, ll;
                    hh.x = h0; hh.y = h1;
                    ll.x = __float2bfloat16(p0 - __bfloat162float(h0));
                    ll.y = __float2bfloat16(p1 - __bfloat162float(h1));
                    pah[kc][half * 2 + pr] = *(uint32_t*)&hh;
                    pal[kc][half * 2 + pr] = *(uint32_t*)&ll;
                }
            }
        }

        #pragma unroll
        for (int kc = 0; kc < 4; ++kc) {
            const int rV = kc * 16 + (lane & 15);
            #pragma unroll
            for (int ni = 0; ni < 8; ++ni) {
                const uint32_t off = (rV << 7) + ((ni ^ (rV & 7)) << 4);
                uint32_t vfh[2], vfl[2];
                ldsm_x2t(vfh, sVh + off);
                ldsm_x2t(vfl, sVl + off);
                mma_bf16(o[ni], pah[kc], vfh);
                mma_bf16(o[ni], pah[kc], vfl);
                mma_bf16(o[ni], pal[kc], vfh);
            }
        }
        __syncthreads();
    }

    const float il0 = 1.0f / l0, il1 = 1.0f / l1;
    const size_t row0 = (size_t)(qrowbase + rl0) * EDIM + colbase + cl0;
    const size_t row1 = (size_t)(qrowbase + rl0 + 8) * EDIM + colbase + cl0;
    #pragma unroll
    for (int ni = 0; ni < 8; ++ni) {
        const int dc = ni * 8;
        float v0 = o[ni][0] * il0, v1 = o[ni][1] * il0;
        float v2 = o[ni][2] * il1, v3 = o[ni][3] * il1;
        __nv_bfloat16 h0 = __float2bfloat16(v0), h1 = __float2bfloat16(v1);
        __nv_bfloat16 h2 = __float2bfloat16(v2), h3 = __float2bfloat16(v3);
        __nv_bfloat162 a, bb, c, d;
        a.x = h0; a.y = h1; c.x = h2; c.y = h3;
        bb.x = __float2bfloat16(v0 - __bfloat162float(h0));
        bb.y = __float2bfloat16(v1 - __bfloat162float(h1));
        d.x = __float2bfloat16(v2 - __bfloat162float(h2));
        d.y = __float2bfloat16(v3 - __bfloat162float(h3));
        *(__nv_bfloat162*)(yh + row0 + dc) = a;
        *(__nv_bfloat162*)(yl + row0 + dc) = bb;
        *(__nv_bfloat162*)(yh + row1 + dc) = c;
        *(__nv_bfloat162*)(yl + row1 + dc) = d;
    }
}

// ---------------------------------------------------------------------------
// lm_head
// ---------------------------------------------------------------------------
__global__ __launch_bounds__(256) void logits_kernel(
    const float* __restrict__ xf, const float* __restrict__ wte,
    const float* __restrict__ lm_b, float* __restrict__ out)
{
    __shared__ float xs[NBATCH * EDIM];
    for (int i = threadIdx.x; i < NBATCH * EDIM; i += 256) xs[i] = xf[i];
    __syncthreads();

    const int warp = threadIdx.x >> 5;
    const int lane = threadIdx.x & 31;
    const int v = blockIdx.x * 8 + warp;

    const float* wrow = wte + (size_t)v * EDIM;
    float acc[NBATCH];
    #pragma unroll
    for (int b = 0; b < NBATCH; ++b) acc[b] = 0.0f;

    for (int k4 = lane * 4; k4 < EDIM; k4 += 128) {
        float4 wv = *(const float4*)(wrow + k4);
        #pragma unroll
        for (int b = 0; b < NBATCH; ++b) {
            float4 xv = *(const float4*)(xs + b * EDIM + k4);
            acc[b] += wv.x*xv.x + wv.y*xv.y + wv.z*xv.z + wv.w*xv.w;
        }
    }
    #pragma unroll
    for (int o = 16; o; o >>= 1)
        #pragma unroll
        for (int b = 0; b < NBATCH; ++b)
            acc[b] += __shfl_xor_sync(0xffffffffu, acc[b], o);

    if (lane == 0) {
        const float bb = lm_b[v];
        #pragma unroll
        for (int b = 0; b < NBATCH; ++b)
            out[(size_t)b * VOCAB + v] = acc[b] + bb;
    }
}

// ---------------------------------------------------------------------------
// Launcher
// ---------------------------------------------------------------------------
extern "C" void kernel_launch(void* const* d_in, const int* in_sizes, int n_in,
                              void* d_out, int out_size)
{
    (void)in_sizes; (void)n_in; (void)out_size;
    const int*   idx    = (const int*)  d_in[0];
    const float* wte    = (const float*)d_in[1];
    const float* wpe    = (const float*)d_in[2];
    const float* qkv_w  = (const float*)d_in[3];
    const float* qkv_b  = (const float*)d_in[4];
    const float* proj_w = (const float*)d_in[5];
    const float* proj_b = (const float*)d_in[6];
    const float* ln_w   = (const float*)d_in[7];
    const float* ln_b   = (const float*)d_in[8];
    const float* c1_w   = (const float*)d_in[9];
    const float* c1_b   = (const float*)d_in[10];
    const float* c2_w   = (const float*)d_in[11];
    const float* c2_b   = (const float*)d_in[12];
    const float* lnf_w  = (const float*)d_in[13];
    const float* lnf_b  = (const float*)d_in[14];
    const float* lm_b   = (const float*)d_in[15];
    float* out = (float*)d_out;

    float *x, *xf;
    __nv_bfloat16 *h_hi, *h_lo, *qv_h, *qv_l, *att_hi, *att_lo, *a1_hi, *a1_lo;
    __nv_bfloat16 *wq_h, *wq_l, *wp_h, *wp_l, *w1_h, *w1_l, *w2_h, *w2_l;
    cudaGetSymbolAddress((void**)&x,     g_x);
    cudaGetSymbolAddress((void**)&xf,    g_xf);
    cudaGetSymbolAddress((void**)&h_hi,  g_h_hi);
    cudaGetSymbolAddress((void**)&h_lo,  g_h_lo);
    cudaGetSymbolAddress((void**)&qv_h,  g_qkv_hi);
    cudaGetSymbolAddress((void**)&qv_l,  g_qkv_lo);
    cudaGetSymbolAddress((void**)&att_hi,g_att_hi);
    cudaGetSymbolAddress((void**)&att_lo,g_att_lo);
    cudaGetSymbolAddress((void**)&a1_hi, g_a1_hi);
    cudaGetSymbolAddress((void**)&a1_lo, g_a1_lo);
    cudaGetSymbolAddress((void**)&wq_h,  g_wqkv_hi);
    cudaGetSymbolAddress((void**)&wq_l,  g_wqkv_lo);
    cudaGetSymbolAddress((void**)&wp_h,  g_wprj_hi);
    cudaGetSymbolAddress((void**)&wp_l,  g_wprj_lo);
    cudaGetSymbolAddress((void**)&w1_h,  g_wc1_hi);
    cudaGetSymbolAddress((void**)&w1_l,  g_wc1_lo);
    cudaGetSymbolAddress((void**)&w2_h,  g_wc2_hi);
    cudaGetSymbolAddress((void**)&w2_l,  g_wc2_lo);

    cudaFuncSetAttribute(attn_kernel,
        cudaFuncAttributeMaxDynamicSharedMemorySize, ATT_SMEM);
    cudaFuncSetAttribute(hmma_gemm<1>,
        cudaFuncAttributeMaxDynamicSharedMemorySize, GEMM_SMEM);
    cudaFuncSetAttribute(hmma_gemm<2>,
        cudaFuncAttributeMaxDynamicSharedMemorySize, GEMM_SMEM);
    cudaFuncSetAttribute(hmma_gemm<3>,
        cudaFuncAttributeMaxDynamicSharedMemorySize, GEMM_SMEM);

    cvt_all_kernel<<<(CVT_TOTAL + 255) / 256, 256>>>(
        qkv_w, wq_h, wq_l, proj_w, wp_h, wp_l,
        c1_w, w1_h, w1_l, c2_w, w2_h, w2_l);

    embed_kernel<<<NTOK, 192>>>(idx, wte, wpe, x);

    for (int l = 0; l < NLAYER; ++l) {
        const float* lw = ln_w + l * EDIM;
        const float* lb = ln_b + l * EDIM;
        const size_t oq = (size_t)l * E3 * EDIM;
        const size_t op = (size_t)l * EDIM * EDIM;
        const size_t o1 = (size_t)l * E4 * EDIM;

        ln_kernel<1><<<NTOK, 256>>>(x, lw, lb, nullptr, h_hi, h_lo, 1, 0);
        hmma_gemm<3><<<dim3(E3 / 256, NTOK / 128), 256, GEMM_SMEM>>>(
            h_hi, h_lo, wq_h + oq, wq_l + oq, qkv_b + (size_t)l * E3,
            nullptr, nullptr, qv_h, qv_l, NTOK, E3, EDIM);
        attn_kernel<<<dim3(TSEQ / 64, NBATCH * NHEAD), 128, ATT_SMEM>>>(
            qv_h, qv_l, att_hi, att_lo);
        hmma_gemm<2><<<dim3(EDIM / 256, NTOK / 128), 256, GEMM_SMEM>>>(
            att_hi, att_lo, wp_h + op, wp_l + op, proj_b + (size_t)l * EDIM,
            x, x, nullptr, nullptr, NTOK, EDIM, EDIM);

        ln_kernel<1><<<NTOK, 256>>>(x, lw, lb, nullptr, h_hi, h_lo, 1, 0);
        hmma_gemm<1><<<dim3(E4 / 256, NTOK / 128), 256, GEMM_SMEM>>>(
            h_hi, h_lo, w1_h + o1, w1_l + o1, c1_b + (size_t)l * E4,
            nullptr, nullptr, a1_hi, a1_lo, NTOK, E4, EDIM);
        hmma_gemm<2><<<dim3(EDIM / 256, NTOK / 128), 256, GEMM_SMEM>>>(
            a1_hi, a1_lo, w2_h + o1, w2_l + o1, c2_b + (size_t)l * EDIM,
            x, x, nullptr, nullptr, NTOK, EDIM, E4);
    }

    ln_kernel<0><<<NBATCH, 256>>>(x, lnf_w, lnf_b, xf, nullptr, nullptr,
                                  TSEQ, TSEQ - 1);
    logits_kernel<<<VOCAB / 8, 256>>>(xf, wte, lm_b, out);
}

// round 13
// speedup vs baseline: 1.1120x; 1.0897x over previous
#include <cuda_runtime.h>
#include <cuda_bf16.h>
#include <math.h>
#include <stdint.h>

// ---------------------------------------------------------------------------
// GPT-2 small forward: B=8, T=1024, E=768, H=12, D=64, L=12, V=50304
// Round 13: shape-specialized GEMMs.
//   wide  (128x256, 64x64 warp tile, 2-stage) for qkv & c1 (large N)
//   narrow(128x128, 64x32 warp tile, 3-stage) for proj & c2 (N=768)
// Attention = round-4 proven config. Fused cvt.
// ---------------------------------------------------------------------------

#define NTOK   8192
#define EDIM   768
#define E3     2304
#define E4     3072
#define NHEAD  12
#define HDIM   64
#define NLAYER 12
#define VOCAB  50304
#define NBATCH 8
#define TSEQ   1024

// ---------------- device scratch (allocation-free) ----------------
__device__ __align__(16) float          g_x    [NTOK * EDIM];
__device__ __align__(16) float          g_xf   [NBATCH * EDIM];
__device__ __align__(16) __nv_bfloat16  g_h_hi  [NTOK * EDIM];
__device__ __align__(16) __nv_bfloat16  g_h_lo  [NTOK * EDIM];
__device__ __align__(16) __nv_bfloat16  g_qkv_hi[NTOK * E3];
__device__ __align__(16) __nv_bfloat16  g_qkv_lo[NTOK * E3];
__device__ __align__(16) __nv_bfloat16  g_att_hi[NTOK * EDIM];
__device__ __align__(16) __nv_bfloat16  g_att_lo[NTOK * EDIM];
__device__ __align__(16) __nv_bfloat16  g_a1_hi [NTOK * E4];
__device__ __align__(16) __nv_bfloat16  g_a1_lo [NTOK * E4];
__device__ __align__(16) __nv_bfloat16  g_wqkv_hi[NLAYER * E3 * EDIM];
__device__ __align__(16) __nv_bfloat16  g_wqkv_lo[NLAYER * E3 * EDIM];
__device__ __align__(16) __nv_bfloat16  g_wprj_hi[NLAYER * EDIM * EDIM];
__device__ __align__(16) __nv_bfloat16  g_wprj_lo[NLAYER * EDIM * EDIM];
__device__ __align__(16) __nv_bfloat16  g_wc1_hi [NLAYER * E4 * EDIM];
__device__ __align__(16) __nv_bfloat16  g_wc1_lo [NLAYER * E4 * EDIM];
__device__ __align__(16) __nv_bfloat16  g_wc2_hi [NLAYER * EDIM * E4];
__device__ __align__(16) __nv_bfloat16  g_wc2_lo [NLAYER * EDIM * E4];

// ---------------- helpers ----------------
__device__ __forceinline__ uint32_t smem_u32(const void* p) {
    uint32_t a;
    asm("{ .reg .u64 t; cvta.to.shared.u64 t, %1; cvt.u32.u64 %0, t; }"
        : "=r"(a) : "l"(p));
    return a;
}
__device__ __forceinline__ void cpa16(uint32_t dst, const void* src) {
    asm volatile("cp.async.cg.shared.global [%0], [%1], 16;" :: "r"(dst), "l"(src));
}
__device__ __forceinline__ void cpa_commit() {
    asm volatile("cp.async.commit_group;" ::: "memory");
}
template<int N> __device__ __forceinline__ void cpa_wait() {
    asm volatile("cp.async.wait_group %0;" :: "n"(N) : "memory");
}
__device__ __forceinline__ void ldsm_x4(uint32_t* r, uint32_t a) {
    asm volatile("ldmatrix.sync.aligned.m8n8.x4.shared.b16 {%0,%1,%2,%3}, [%4];"
        : "=r"(r[0]), "=r"(r[1]), "=r"(r[2]), "=r"(r[3]) : "r"(a));
}
__device__ __forceinline__ void ldsm_x4p(uint32_t* r0, uint32_t* r1, uint32_t a) {
    asm volatile("ldmatrix.sync.aligned.m8n8.x4.shared.b16 {%0,%1,%2,%3}, [%4];"
        : "=r"(r0[0]), "=r"(r0[1]), "=r"(r1[0]), "=r"(r1[1]) : "r"(a));
}
__device__ __forceinline__ void ldsm_x2(uint32_t* r, uint32_t a) {
    asm volatile("ldmatrix.sync.aligned.m8n8.x2.shared.b16 {%0,%1}, [%2];"
        : "=r"(r[0]), "=r"(r[1]) : "r"(a));
}
__device__ __forceinline__ void ldsm_x2t(uint32_t* r, uint32_t a) {
    asm volatile("ldmatrix.sync.aligned.m8n8.x2.trans.shared.b16 {%0,%1}, [%2];"
        : "=r"(r[0]), "=r"(r[1]) : "r"(a));
}
__device__ __forceinline__ void mma_bf16(float* c, const uint32_t* a,
                                         const uint32_t* b) {
    asm volatile(
        "mma.sync.aligned.m16n8k16.row.col.f32.bf16.bf16.f32 "
        "{%0,%1,%2,%3}, {%4,%5,%6,%7}, {%8,%9}, {%0,%1,%2,%3};"
        : "+f"(c[0]), "+f"(c[1]), "+f"(c[2]), "+f"(c[3])
        : "r"(a[0]), "r"(a[1]), "r"(a[2]), "r"(a[3]), "r"(b[0]), "r"(b[1]));
}
__device__ __forceinline__ float gelu_exact(float v) {
    return 0.5f * v * (1.0f + erff(v * 0.70710678118654752f));
}

// ---------------------------------------------------------------------------
// Fused weight convert
// ---------------------------------------------------------------------------
__device__ __forceinline__ void cvt4(const float* w, __nv_bfloat16* hi,
                                     __nv_bfloat16* lo, int i) {
    float4 v = ((const float4*)w)[i];
    __nv_bfloat16 h0 = __float2bfloat16(v.x), h1 = __float2bfloat16(v.y);
    __nv_bfloat16 h2 = __float2bfloat16(v.z), h3 = __float2bfloat16(v.w);
    __nv_bfloat162 hh0, hh1, ll0, ll1;
    hh0.x = h0; hh0.y = h1; hh1.x = h2; hh1.y = h3;
    ll0.x = __float2bfloat16(v.x - __bfloat162float(h0));
    ll0.y = __float2bfloat16(v.y - __bfloat162float(h1));
    ll1.x = __float2bfloat16(v.z - __bfloat162float(h2));
    ll1.y = __float2bfloat16(v.w - __bfloat162float(h3));
    ((__nv_bfloat162*)hi)[i * 2 + 0] = hh0;
    ((__nv_bfloat162*)hi)[i * 2 + 1] = hh1;
    ((__nv_bfloat162*)lo)[i * 2 + 0] = ll0;
    ((__nv_bfloat162*)lo)[i * 2 + 1] = ll1;
}

#define NQ4 (NLAYER * E3 * EDIM / 4)
#define NP4 (NLAYER * EDIM * EDIM / 4)
#define N14 (NLAYER * E4 * EDIM / 4)

__global__ __launch_bounds__(256) void cvt_all_kernel(
    const float* __restrict__ wq, __nv_bfloat16* __restrict__ wqh,
    __nv_bfloat16* __restrict__ wql,
    const float* __restrict__ wp, __nv_bfloat16* __restrict__ wph,
    __nv_bfloat16* __restrict__ wpl,
    const float* __restrict__ w1, __nv_bfloat16* __restrict__ w1h,
    __nv_bfloat16* __restrict__ w1l,
    const float* __restrict__ w2, __nv_bfloat16* __restrict__ w2h,
    __nv_bfloat16* __restrict__ w2l)
{
    int i = blockIdx.x * 256 + threadIdx.x;
    if (i < NQ4) { cvt4(wq, wqh, wql, i); return; }
    i -= NQ4;
    if (i < NP4) { cvt4(wp, wph, wpl, i); return; }
    i -= NP4;
    if (i < N14) { cvt4(w1, w1h, w1l, i); return; }
    i -= N14;
    if (i < N14) { cvt4(w2, w2h, w2l, i); }
}
#define CVT_TOTAL (NQ4 + NP4 + 2 * N14)

// ---------------------------------------------------------------------------
// Embedding
// ---------------------------------------------------------------------------
__global__ __launch_bounds__(192) void embed_kernel(
    const int* __restrict__ idx, const float* __restrict__ wte,
    const float* __restrict__ wpe, float* __restrict__ x)
{
    const int n = blockIdx.x;
    const int t = n & (TSEQ - 1);
    const int tok = idx[n];
    const float4* pw = (const float4*)(wte + (size_t)tok * EDIM);
    const float4* pp = (const float4*)(wpe + (size_t)t * EDIM);
    float4* po = (float4*)(x + (size_t)n * EDIM);
    const int i = threadIdx.x;
    float4 a = pw[i], b = pp[i];
    po[i] = make_float4(a.x + b.x, a.y + b.y, a.z + b.z, a.w + b.w);
}

// ---------------------------------------------------------------------------
// LayerNorm.  OUTM=0 -> fp32 out; OUTM=1 -> bf16 hi/lo pair
// ---------------------------------------------------------------------------
template<int OUTM>
__global__ __launch_bounds__(256) void ln_kernel(
    const float* __restrict__ x, const float* __restrict__ w,
    const float* __restrict__ b, float* __restrict__ outf,
    __nv_bfloat16* __restrict__ outh, __nv_bfloat16* __restrict__ outl,
    int stride, int offset)
{
    __shared__ float red[8];
    const int row = blockIdx.x * stride + offset;
    const float* px = x + (size_t)row * EDIM;
    const int tid = threadIdx.x;

    float v0 = px[tid], v1 = px[tid + 256], v2 = px[tid + 512];
    float s = v0 + v1 + v2;
    #pragma unroll
    for (int o = 16; o; o >>= 1) s += __shfl_xor_sync(0xffffffffu, s, o);
    if ((tid & 31) == 0) red[tid >> 5] = s;
    __syncthreads();
    float tot = red[0]+red[1]+red[2]+red[3]+red[4]+red[5]+red[6]+red[7];
    const float mu = tot * (1.0f / EDIM);

    float d0 = v0 - mu, d1 = v1 - mu, d2 = v2 - mu;
    float q = d0*d0 + d1*d1 + d2*d2;
    #pragma unroll
    for (int o = 16; o; o >>= 1) q += __shfl_xor_sync(0xffffffffu, q, o);
    __syncthreads();
    if ((tid & 31) == 0) red[tid >> 5] = q;
    __syncthreads();
    float qt = red[0]+red[1]+red[2]+red[3]+red[4]+red[5]+red[6]+red[7];
    const float rstd = rsqrtf(qt * (1.0f / EDIM) + 1e-5f);

    const size_t ob = (size_t)blockIdx.x * EDIM;
    #pragma unroll
    for (int c = 0; c < 3; ++c) {
        const int col = tid + c * 256;
        const float dd = (c == 0 ? d0 : (c == 1 ? d1 : d2));
        float v = dd * rstd * w[col] + b[col];
        if (OUTM == 0) {
            outf[ob + col] = v;
        } else {
            __nv_bfloat16 h = __float2bfloat16(v);
            outh[ob + col] = h;
            outl[ob + col] = __float2bfloat16(v - __bfloat162float(h));
        }
    }
}

// ===========================================================================
// WIDE GEMM: 128x256 CTA, 8 warps, warp tile 64x64, BK=64, 2 stages x 96KB.
// For qkv (MODE 3) and c1 (MODE 1).
// ===========================================================================
#define WSTG_BYTES 98304
#define WGEMM_SMEM (2 * WSTG_BYTES)

__device__ __forceinline__ void w_load_stage(
    uint32_t sbase,
    const __nv_bfloat16* __restrict__ Ah, const __nv_bfloat16* __restrict__ Al,
    const __nv_bfloat16* __restrict__ Bh, const __nv_bfloat16* __restrict__ Bl,
    int K, int k0, int tid)
{
    #pragma unroll
    for (int half = 0; half < 2; ++half) {
        const __nv_bfloat16* S = half ? Al : Ah;
        const uint32_t base = sbase + half * 16384;
        #pragma unroll
        for (int it = 0; it < 4; ++it) {
            const int i = tid + it * 256;
            const int row = i >> 3, c = i & 7;
            cpa16(base + (row << 7) + ((c ^ (row & 7)) << 4),
                  S + (size_t)row * K + k0 + c * 8);
        }
    }
    #pragma unroll
    for (int half = 0; half < 2; ++half) {
        const __nv_bfloat16* S = half ? Bl : Bh;
        const uint32_t base = sbase + 32768 + half * 32768;
        #pragma unroll
        for (int it = 0; it < 8; ++it) {
            const int i = tid + it * 256;
            const int row = i >> 3, c = i & 7;
            cpa16(base + (row << 7) + ((c ^ (row & 7)) << 4),
                  S + (size_t)row * K + k0 + c * 8);
        }
    }
    cpa_commit();
}

template<int MODE>
__global__ __launch_bounds__(256) void hmma_gemm_w(
    const __nv_bfloat16* __restrict__ Ah, const __nv_bfloat16* __restrict__ Al,
    const __nv_bfloat16* __restrict__ Bh, const __nv_bfloat16* __restrict__ Bl,
    const float* __restrict__ bias,
    float* __restrict__ Cf, __nv_bfloat16* __restrict__ Ch,
    __nv_bfloat16* __restrict__ Cl, int M, int N, int K)
{
    extern __shared__ char smem[];
    const uint32_t sb = smem_u32(smem);
    const int tid = threadIdx.x;
    const int wid = tid >> 5;
    const int lane = tid & 31;
    const int wm = wid >> 2;
    const int wn = wid & 3;
    const int bm = blockIdx.y * 128;
    const int bn = blockIdx.x * 256;

    const int nkk = K >> 6;

    Ah += (size_t)bm * K; Al += (size_t)bm * K;
    Bh += (size_t)bn * K; Bl += (size_t)bn * K;

    w_load_stage(sb, Ah, Al, Bh, Bl, K, 0, tid);
    w_load_stage(sb + WSTG_BYTES, Ah, Al, Bh, Bl, K, 64, tid);

    float acc[4][8][4];
    #pragma unroll
    for (int i = 0; i < 4; ++i)
        #pragma unroll
        for (int j = 0; j < 8; ++j)
            #pragma unroll
            for (int q = 0; q < 4; ++q) acc[i][j][q] = 0.0f;

    const int arow = wm * 64 + (lane & 15);
    const int akoff = (lane >> 4);
    const int brow = wn * 64 + (lane & 7) + ((lane >> 4) << 3);
    const int bkoff = ((lane >> 3) & 1);

    for (int kt = 0; kt < nkk; ++kt) {
        cpa_wait<1>();
        __syncthreads();

        const uint32_t sA  = sb + (uint32_t)(kt & 1) * WSTG_BYTES;
        const uint32_t sAl = sA + 16384;
        const uint32_t sBh = sA + 32768;
        const uint32_t sBl = sA + 65536;

        #pragma unroll
        for (int ks = 0; ks < 4; ++ks) {
            uint32_t afh[4][4], afl[4][4], bfh[8][2], bfl[8][2];
            const int kc = ks * 2 + akoff;
            #pragma unroll
            for (int mi = 0; mi < 4; ++mi) {
                const int r = arow + mi * 16;
                const uint32_t off = (r << 7) + ((kc ^ (r & 7)) << 4);
                ldsm_x4(afh[mi], sA + off);
                ldsm_x4(afl[mi], sAl + off);
            }
            const int kcb = ks * 2 + bkoff;
            #pragma unroll
            for (int p = 0; p < 4; ++p) {
                const int r = brow + p * 16;
                const uint32_t off = (r << 7) + ((kcb ^ (r & 7)) << 4);
                ldsm_x4p(bfh[p * 2], bfh[p * 2 + 1], sBh + off);
                ldsm_x4p(bfl[p * 2], bfl[p * 2 + 1], sBl + off);
            }
            #pragma unroll
            for (int ni = 0; ni < 8; ++ni)
                #pragma unroll
                for (int mi = 0; mi < 4; ++mi) {
                    mma_bf16(acc[mi][ni], afh[mi], bfh[ni]);
                    mma_bf16(acc[mi][ni], afh[mi], bfl[ni]);
                    mma_bf16(acc[mi][ni], afl[mi], bfh[ni]);
                }
        }

        __syncthreads();
        if (kt + 2 < nkk) {
            w_load_stage(sA, Ah, Al, Bh, Bl, K, (kt + 2) * 64, tid);
        } else {
            cpa_commit();
        }
    }

    const int grp = lane >> 2;
    const int tig = lane & 3;
    #pragma unroll
    for (int mi = 0; mi < 4; ++mi) {
        #pragma unroll
        for (int half = 0; half < 2; ++half) {
            const int grow = bm + wm * 64 + mi * 16 + grp + half * 8;
            #pragma unroll
            for (int ni = 0; ni < 8; ++ni) {
                const int gcol = bn + wn * 64 + ni * 8 + tig * 2;
                float v0 = acc[mi][ni][half * 2 + 0] + bias[gcol];
                float v1 = acc[mi][ni][half * 2 + 1] + bias[gcol + 1];
                if (MODE == 1) { v0 = gelu_exact(v0); v1 = gelu_exact(v1); }
                __nv_bfloat16 h0 = __float2bfloat16(v0);
                __nv_bfloat16 h1 = __float2bfloat16(v1);
                __nv_bfloat162 hh, ll;
                hh.x = h0; hh.y = h1;
                ll.x = __float2bfloat16(v0 - __bfloat162float(h0));
                ll.y = __float2bfloat16(v1 - __bfloat162float(h1));
                *(__nv_bfloat162*)(Ch + (size_t)grow * N + gcol) = hh;
                *(__nv_bfloat162*)(Cl + (size_t)grow * N + gcol) = ll;
            }
        }
    }
}

// ===========================================================================
// NARROW GEMM (round-10): 128x128 CTA, 8 warps, warp tile 64x32, BK=64,
// 3 stages x 64KB, fragment double buffer. For proj & c2 (MODE 2, +residual).
// ===========================================================================
#define NSTG_BYTES 65536
#define NGEMM_SMEM (3 * NSTG_BYTES)

__device__ __forceinline__ void n_load_stage(
    uint32_t sbase,
    const __nv_bfloat16* __restrict__ Ah, const __nv_bfloat16* __restrict__ Al,
    const __nv_bfloat16* __restrict__ Bh, const __nv_bfloat16* __restrict__ Bl,
    int K, int k0, int tid)
{
    const __nv_bfloat16* srcs[4] = { Ah, Al, Bh, Bl };
    #pragma unroll
    for (int t4 = 0; t4 < 4; ++t4) {
        const __nv_bfloat16* S = srcs[t4];
        const uint32_t base = sbase + t4 * 16384;
        #pragma unroll
        for (int it = 0; it < 4; ++it) {
            const int i = tid + it * 256;
            const int row = i >> 3, c = i & 7;
            cpa16(base + (row << 7) + ((c ^ (row & 7)) << 4),
                  S + (size_t)row * K + k0 + c * 8);
        }
    }
    cpa_commit();
}

__global__ __launch_bounds__(256, 1) void hmma_gemm_n(
    const __nv_bfloat16* __restrict__ Ah, const __nv_bfloat16* __restrict__ Al,
    const __nv_bfloat16* __restrict__ Bh, const __nv_bfloat16* __restrict__ Bl,
    const float* __restrict__ bias, const float* __restrict__ R,
    float* __restrict__ Cf, int M, int N, int K)
{
    extern __shared__ char smem[];
    const uint32_t sb = smem_u32(smem);
    const int tid = threadIdx.x;
    const int wid = tid >> 5;
    const int lane = tid & 31;
    const int wm = wid >> 2;
    const int wn = wid & 3;
    const int bm = blockIdx.y * 128;
    const int bn = blockIdx.x * 128;

    const int nkk = K >> 6;

    Ah += (size_t)bm * K; Al += (size_t)bm * K;
    Bh += (size_t)bn * K; Bl += (size_t)bn * K;

    n_load_stage(sb, Ah, Al, Bh, Bl, K, 0, tid);
    n_load_stage(sb + NSTG_BYTES, Ah, Al, Bh, Bl, K, 64, tid);

    float acc[4][4][4];
    #pragma unroll
    for (int i = 0; i < 4; ++i)
        #pragma unroll
        for (int j = 0; j < 4; ++j)
            #pragma unroll
            for (int q = 0; q < 4; ++q) acc[i][j][q] = 0.0f;

    const int arow = wm * 64 + (lane & 15);
    const int akoff = (lane >> 4);
    const int brow_base = wn * 32 + (lane & 7);
    const int bkoff = ((lane >> 3) & 1);

    uint32_t afh[2][4][4], afl[2][4][4], bfh[2][4][2], bfl[2][4][2];

    for (int kt = 0; kt < nkk; ++kt) {
        cpa_wait<1>();
        __syncthreads();

        if (kt + 2 < nkk) {
            n_load_stage(sb + (uint32_t)((kt + 2) % 3) * NSTG_BYTES,
                         Ah, Al, Bh, Bl, K, (kt + 2) * 64, tid);
        } else {
            cpa_commit();
        }

        const uint32_t sA  = sb + (uint32_t)(kt % 3) * NSTG_BYTES;
        const uint32_t sAl = sA + 16384;
        const uint32_t sBh = sA + 32768;
        const uint32_t sBl = sA + 49152;

        {
            const int kc = akoff;
            #pragma unroll
            for (int mi = 0; mi < 4; ++mi) {
                const int r = arow + mi * 16;
                const uint32_t off = (r << 7) + ((kc ^ (r & 7)) << 4);
                ldsm_x4(afh[0][mi], sA + off);
                ldsm_x4(afl[0][mi], sAl + off);
            }
            const int kcb = bkoff;
            #pragma unroll
            for (int ni = 0; ni < 4; ++ni) {
                const int r = brow_base + ni * 8;
                const uint32_t off = (r << 7) + ((kcb ^ (r & 7)) << 4);
                ldsm_x2(bfh[0][ni], sBh + off);
                ldsm_x2(bfl[0][ni], sBl + off);
            }
        }

        #pragma unroll
        for (int ks = 0; ks < 4; ++ks) {
            const int cur = ks & 1;
            if (ks < 3) {
                const int nxt = cur ^ 1;
                const int kc = (ks + 1) * 2 + akoff;
                #pragma unroll
                for (int mi = 0; mi < 4; ++mi) {
                    const int r = arow + mi * 16;
                    const uint32_t off = (r << 7) + ((kc ^ (r & 7)) << 4);
                    ldsm_x4(afh[nxt][mi], sA + off);
                    ldsm_x4(afl[nxt][mi], sAl + off);
                }
                const int kcb = (ks + 1) * 2 + bkoff;
                #pragma unroll
                for (int ni = 0; ni < 4; ++ni) {
                    const int r = brow_base + ni * 8;
                    const uint32_t off = (r << 7) + ((kcb ^ (r & 7)) << 4);
                    ldsm_x2(bfh[nxt][ni], sBh + off);
                    ldsm_x2(bfl[nxt][ni], sBl + off);
                }
            }
            #pragma unroll
            for (int ni = 0; ni < 4; ++ni)
                #pragma unroll
                for (int mi = 0; mi < 4; ++mi) {
                    mma_bf16(acc[mi][ni], afh[cur][mi], bfh[cur][ni]);
                    mma_bf16(acc[mi][ni], afh[cur][mi], bfl[cur][ni]);
                    mma_bf16(acc[mi][ni], afl[cur][mi], bfh[cur][ni]);
                }
        }
    }

    const int grp = lane >> 2;
    const int tig = lane & 3;
    #pragma unroll
    for (int mi = 0; mi < 4; ++mi) {
        #pragma unroll
        for (int half = 0; half < 2; ++half) {
            const int grow = bm + wm * 64 + mi * 16 + grp + half * 8;
            #pragma unroll
            for (int ni = 0; ni < 4; ++ni) {
                const int gcol = bn + wn * 32 + ni * 8 + tig * 2;
                float v0 = acc[mi][ni][half * 2 + 0] + bias[gcol];
                float v1 = acc[mi][ni][half * 2 + 1] + bias[gcol + 1];
                float2 rr = *(const float2*)(R + (size_t)grow * N + gcol);
                *(float2*)(Cf + (size_t)grow * N + gcol) =
                    make_float2(v0 + rr.x, v1 + rr.y);
            }
        }
    }
}

// ---------------------------------------------------------------------------
// HMMA flash attention (round-4 double-buffered config). Heavy q-tiles first.
// ---------------------------------------------------------------------------
#define ATT_SMEM (16384 + 2 * 32768)

__device__ __forceinline__ void attn_stage_load(
    uint32_t sbase, const __nv_bfloat16* __restrict__ qh,
    const __nv_bfloat16* __restrict__ ql, int growbase, int colbase, int tid)
{
    #pragma unroll
    for (int it = 0; it < 16; ++it) {
        const int i = tid + it * 128;
        const int tile = i >> 9;
        const int r = (i >> 3) & 63;
        const int c = i & 7;
        const __nv_bfloat16* arr = (tile & 1) ? ql : qh;
        const int seg = (tile >> 1) ? 2 * EDIM : 0;
        cpa16(sbase + tile * 8192 + (r << 7) + ((c ^ (r & 7)) << 4),
              arr + (size_t)(growbase + r) * E3 + seg + colbase + c * 8);
    }
}

__global__ __launch_bounds__(128, 2) void attn_kernel(
    const __nv_bfloat16* __restrict__ qh, const __nv_bfloat16* __restrict__ ql,
    __nv_bfloat16* __restrict__ yh, __nv_bfloat16* __restrict__ yl)
{
    extern __shared__ char smem[];
    const uint32_t sb = smem_u32(smem);
    const int tid = threadIdx.x;
    const int w = tid >> 5;
    const int lane = tid & 31;
    const int qt = gridDim.x - 1 - blockIdx.x;
    const int bh = blockIdx.y;
    const int b = bh / NHEAD;
    const int hh = bh % NHEAD;
    const int colbase = hh * HDIM;
    const int qrowbase = b * TSEQ + qt * 64;

    #pragma unroll
    for (int it = 0; it < 8; ++it) {
        const int i = tid + it * 128;
        const int tile = i >> 9;
        const int r = (i >> 3) & 63;
        const int c = i & 7;
        const __nv_bfloat16* arr = tile ? ql : qh;
        cpa16(sb + tile * 8192 + (r << 7) + ((c ^ (r & 7)) << 4),
              arr + (size_t)(qrowbase + r) * E3 + EDIM + colbase + c * 8);
    }
    attn_stage_load(sb + 16384, qh, ql, b * TSEQ, colbase, tid);
    cpa_commit();

    uint32_t qfh[4][4], qfl[4][4];
    float o[8][4];
    #pragma unroll
    for (int ni = 0; ni < 8; ++ni)
        #pragma unroll
        for (int q = 0; q < 4; ++q) o[ni][q] = 0.0f;
    float m0 = -1e30f, m1 = -1e30f, l0 = 0.0f, l1 = 0.0f;

    const uint32_t stg[2] = { sb + 16384, sb + 16384 + 32768 };
    const int rl0 = w * 16 + (lane >> 2);
    const int cl0 = (lane & 3) * 2;

    for (int kt = 0; kt <= qt; ++kt) {
        if (kt + 1 <= qt)
            attn_stage_load(stg[(kt + 1) & 1], qh, ql,
                            b * TSEQ + (kt + 1) * 64, colbase, tid);
        cpa_commit();
        cpa_wait<1>();
        __syncthreads();

        if (kt == 0) {
            const int r = w * 16 + (lane & 15);
            #pragma unroll
            for (int ks = 0; ks < 4; ++ks) {
                const int kc = ks * 2 + (lane >> 4);
                const uint32_t off = (r << 7) + ((kc ^ (r & 7)) << 4);
                ldsm_x4(qfh[ks], sb + off);
                ldsm_x4(qfl[ks], sb + 8192 + off);
            }
        }

        const uint32_t sKh = stg[kt & 1];
        const uint32_t sKl = sKh + 8192;
        const uint32_t sVh = sKh + 16384;
        const uint32_t sVl = sKh + 24576;

        float s[8][4];
        #pragma unroll
        for (int ni = 0; ni < 8; ++ni)
            #pragma unroll
            for (int q = 0; q < 4; ++q) s[ni][q] = 0.0f;

        #pragma unroll
        for (int ks = 0; ks < 4; ++ks) {
            const int kcb = ks * 2 + ((lane >> 3) & 1);
            #pragma unroll
            for (int ni = 0; ni < 8; ++ni) {
                const int r = ni * 8 + (lane & 7);
                const uint32_t off = (r << 7) + ((kcb ^ (r & 7)) << 4);
                uint32_t kfh[2], kfl[2];
                ldsm_x2(kfh, sKh + off);
                ldsm_x2(kfl, sKl + off);
                mma_bf16(s[ni], qfh[ks], kfh);
                mma_bf16(s[ni], qfh[ks], kfl);
                mma_bf16(s[ni], qfl[ks], kfh);
            }
        }

        if (kt == qt) {
            #pragma unroll
            for (int ni = 0; ni < 8; ++ni) {
                const int c0 = ni * 8 + cl0;
                if (c0 > rl0)     s[ni][0] = -1e30f;
                if (c0 + 1 > rl0) s[ni][1] = -1e30f;
                if (c0 > rl0 + 8)     s[ni][2] = -1e30f;
                if (c0 + 1 > rl0 + 8) s[ni][3] = -1e30f;
            }
        }

        float mx0 = -1e30f, mx1 = -1e30f;
        #pragma unroll
        for (int ni = 0; ni < 8; ++ni) {
            mx0 = fmaxf(mx0, fmaxf(s[ni][0], s[ni][1]));
            mx1 = fmaxf(mx1, fmaxf(s[ni][2], s[ni][3]));
        }
        mx0 = fmaxf(mx0, __shfl_xor_sync(0xffffffffu, mx0, 1, 4));
        mx0 = fmaxf(mx0, __shfl_xor_sync(0xffffffffu, mx0, 2, 4));
        mx1 = fmaxf(mx1, __shfl_xor_sync(0xffffffffu, mx1, 1, 4));
        mx1 = fmaxf(mx1, __shfl_xor_sync(0xffffffffu, mx1, 2, 4));
        const float nm0 = fmaxf(m0, mx0), nm1 = fmaxf(m1, mx1);
        const float al0 = __expf(m0 - nm0), al1 = __expf(m1 - nm1);
        float rs0 = 0.0f, rs1 = 0.0f;
        #pragma unroll
        for (int ni = 0; ni < 8; ++ni) {
            s[ni][0] = __expf(s[ni][0] - nm0); rs0 += s[ni][0];
            s[ni][1] = __expf(s[ni][1] - nm0); rs0 += s[ni][1];
            s[ni][2] = __expf(s[ni][2] - nm1); rs1 += s[ni][2];
            s[ni][3] = __expf(s[ni][3] - nm1); rs1 += s[ni][3];
        }
        rs0 += __shfl_xor_sync(0xffffffffu, rs0, 1, 4);
        rs0 += __shfl_xor_sync(0xffffffffu, rs0, 2, 4);
        rs1 += __shfl_xor_sync(0xffffffffu, rs1, 1, 4);
        rs1 += __shfl_xor_sync(0xffffffffu, rs1, 2, 4);
        l0 = l0 * al0 + rs0; m0 = nm0;
        l1 = l1 * al1 + rs1; m1 = nm1;
        #pragma unroll
        for (int ni = 0; ni < 8; ++ni) {
            o[ni][0] *= al0; o[ni][1] *= al0;
            o[ni][2] *= al1; o[ni][3] *= al1;
        }

        uint32_t pah[4][4], pal[4][4];
        #pragma unroll
        for (int kc = 0; kc < 4; ++kc) {
            #pragma unroll
            for (int half = 0; half < 2; ++half) {
                const int ni = kc * 2 + half;
                #pragma unroll
                for (int pr = 0; pr < 2; ++pr) {
                    float p0 = s[ni][pr * 2 + 0];
                    float p1 = s[ni][pr * 2 + 1];
                    __nv_bfloat16 h0 = __float2bfloat16(p0);
                    __nv_bfloat16 h1 = __float2bfloat16(p1);
                    __nv_bfloat162 hh, ll;
                    hh.x = h0; hh.y = h1;
                    ll.x = __float2bfloat16(p0 - __bfloat162float(h0));
                    ll.y = __float2bfloat16(p1 - __bfloat162float(h1));
                    pah[kc][half * 2 + pr] = *(uint32_t*)&hh;
                    pal[kc][half * 2 + pr] = *(uint32_t*)&ll;
                }
            }
        }

        #pragma unroll
        for (int kc = 0; kc < 4; ++kc) {
            const int rV = kc * 16 + (lane & 15);
            #pragma unroll
            for (int ni = 0; ni < 8; ++ni) {
                const uint32_t off = (rV << 7) + ((ni ^ (rV & 7)) << 4);
                uint32_t vfh[2], vfl[2];
                ldsm_x2t(vfh, sVh + off);
                ldsm_x2t(vfl, sVl + off);
                mma_bf16(o[ni], pah[kc], vfh);
                mma_bf16(o[ni], pah[kc], vfl);
                mma_bf16(o[ni], pal[kc], vfh);
            }
        }
        __syncthreads();
    }

    const float il0 = 1.0f / l0, il1 = 1.0f / l1;
    const size_t row0 = (size_t)(qrowbase + rl0) * EDIM + colbase + cl0;
    const size_t row1 = (size_t)(qrowbase + rl0 + 8) * EDIM + colbase + cl0;
    #pragma unroll
    for (int ni = 0; ni < 8; ++ni) {
        const int dc = ni * 8;
        float v0 = o[ni][0] * il0, v1 = o[ni][1] * il0;
        float v2 = o[ni][2] * il1, v3 = o[ni][3] * il1;
        __nv_bfloat16 h0 = __float2bfloat16(v0), h1 = __float2bfloat16(v1);
        __nv_bfloat16 h2 = __float2bfloat16(v2), h3 = __float2bfloat16(v3);
        __nv_bfloat162 a, bb, c, d;
        a.x = h0; a.y = h1; c.x = h2; c.y = h3;
        bb.x = __float2bfloat16(v0 - __bfloat162float(h0));
        bb.y = __float2bfloat16(v1 - __bfloat162float(h1));
        d.x = __float2bfloat16(v2 - __bfloat162float(h2));
        d.y = __float2bfloat16(v3 - __bfloat162float(h3));
        *(__nv_bfloat162*)(yh + row0 + dc) = a;
        *(__nv_bfloat162*)(yl + row0 + dc) = bb;
        *(__nv_bfloat162*)(yh + row1 + dc) = c;
        *(__nv_bfloat162*)(yl + row1 + dc) = d;
    }
}

// ---------------------------------------------------------------------------
// lm_head
// ---------------------------------------------------------------------------
__global__ __launch_bounds__(256) void logits_kernel(
    const float* __restrict__ xf, const float* __restrict__ wte,
    const float* __restrict__ lm_b, float* __restrict__ out)
{
    __shared__ float xs[NBATCH * EDIM];
    for (int i = threadIdx.x; i < NBATCH * EDIM; i += 256) xs[i] = xf[i];
    __syncthreads();

    const int warp = threadIdx.x >> 5;
    const int lane = threadIdx.x & 31;
    const int v = blockIdx.x * 8 + warp;

    const float* wrow = wte + (size_t)v * EDIM;
    float acc[NBATCH];
    #pragma unroll
    for (int b = 0; b < NBATCH; ++b) acc[b] = 0.0f;

    for (int k4 = lane * 4; k4 < EDIM; k4 += 128) {
        float4 wv = *(const float4*)(wrow + k4);
        #pragma unroll
        for (int b = 0; b < NBATCH; ++b) {
            float4 xv = *(const float4*)(xs + b * EDIM + k4);
            acc[b] += wv.x*xv.x + wv.y*xv.y + wv.z*xv.z + wv.w*xv.w;
        }
    }
    #pragma unroll
    for (int o = 16; o; o >>= 1)
        #pragma unroll
        for (int b = 0; b < NBATCH; ++b)
            acc[b] += __shfl_xor_sync(0xffffffffu, acc[b], o);

    if (lane == 0) {
        const float bb = lm_b[v];
        #pragma unroll
        for (int b = 0; b < NBATCH; ++b)
            out[(size_t)b * VOCAB + v] = acc[b] + bb;
    }
}

// ---------------------------------------------------------------------------
// Launcher
// ---------------------------------------------------------------------------
extern "C" void kernel_launch(void* const* d_in, const int* in_sizes, int n_in,
                              void* d_out, int out_size)
{
    (void)in_sizes; (void)n_in; (void)out_size;
    const int*   idx    = (const int*)  d_in[0];
    const float* wte    = (const float*)d_in[1];
    const float* wpe    = (const float*)d_in[2];
    const float* qkv_w  = (const float*)d_in[3];
    const float* qkv_b  = (const float*)d_in[4];
    const float* proj_w = (const float*)d_in[5];
    const float* proj_b = (const float*)d_in[6];
    const float* ln_w   = (const float*)d_in[7];
    const float* ln_b   = (const float*)d_in[8];
    const float* c1_w   = (const float*)d_in[9];
    const float* c1_b   = (const float*)d_in[10];
    const float* c2_w   = (const float*)d_in[11];
    const float* c2_b   = (const float*)d_in[12];
    const float* lnf_w  = (const float*)d_in[13];
    const float* lnf_b  = (const float*)d_in[14];
    const float* lm_b   = (const float*)d_in[15];
    float* out = (float*)d_out;

    float *x, *xf;
    __nv_bfloat16 *h_hi, *h_lo, *qv_h, *qv_l, *att_hi, *att_lo, *a1_hi, *a1_lo;
    __nv_bfloat16 *wq_h, *wq_l, *wp_h, *wp_l, *w1_h, *w1_l, *w2_h, *w2_l;
    cudaGetSymbolAddress((void**)&x,     g_x);
    cudaGetSymbolAddress((void**)&xf,    g_xf);
    cudaGetSymbolAddress((void**)&h_hi,  g_h_hi);
    cudaGetSymbolAddress((void**)&h_lo,  g_h_lo);
    cudaGetSymbolAddress((void**)&qv_h,  g_qkv_hi);
    cudaGetSymbolAddress((void**)&qv_l,  g_qkv_lo);
    cudaGetSymbolAddress((void**)&att_hi,g_att_hi);
    cudaGetSymbolAddress((void**)&att_lo,g_att_lo);
    cudaGetSymbolAddress((void**)&a1_hi, g_a1_hi);
    cudaGetSymbolAddress((void**)&a1_lo, g_a1_lo);
    cudaGetSymbolAddress((void**)&wq_h,  g_wqkv_hi);
    cudaGetSymbolAddress((void**)&wq_l,  g_wqkv_lo);
    cudaGetSymbolAddress((void**)&wp_h,  g_wprj_hi);
    cudaGetSymbolAddress((void**)&wp_l,  g_wprj_lo);
    cudaGetSymbolAddress((void**)&w1_h,  g_wc1_hi);
    cudaGetSymbolAddress((void**)&w1_l,  g_wc1_lo);
    cudaGetSymbolAddress((void**)&w2_h,  g_wc2_hi);
    cudaGetSymbolAddress((void**)&w2_l,  g_wc2_lo);

    cudaFuncSetAttribute(attn_kernel,
        cudaFuncAttributeMaxDynamicSharedMemorySize, ATT_SMEM);
    cudaFuncSetAttribute(hmma_gemm_w<1>,
        cudaFuncAttributeMaxDynamicSharedMemorySize, WGEMM_SMEM);
    cudaFuncSetAttribute(hmma_gemm_w<3>,
        cudaFuncAttributeMaxDynamicSharedMemorySize, WGEMM_SMEM);
    cudaFuncSetAttribute(hmma_gemm_n,
        cudaFuncAttributeMaxDynamicSharedMemorySize, NGEMM_SMEM);

    cvt_all_kernel<<<(CVT_TOTAL + 255) / 256, 256>>>(
        qkv_w, wq_h, wq_l, proj_w, wp_h, wp_l,
        c1_w, w1_h, w1_l, c2_w, w2_h, w2_l);

    embed_kernel<<<NTOK, 192>>>(idx, wte, wpe, x);

    for (int l = 0; l < NLAYER; ++l) {
        const float* lw = ln_w + l * EDIM;
        const float* lb = ln_b + l * EDIM;
        const size_t oq = (size_t)l * E3 * EDIM;
        const size_t op = (size_t)l * EDIM * EDIM;
        const size_t o1 = (size_t)l * E4 * EDIM;

        ln_kernel<1><<<NTOK, 256>>>(x, lw, lb, nullptr, h_hi, h_lo, 1, 0);
        hmma_gemm_w<3><<<dim3(E3 / 256, NTOK / 128), 256, WGEMM_SMEM>>>(
            h_hi, h_lo, wq_h + oq, wq_l + oq, qkv_b + (size_t)l * E3,
            nullptr, qv_h, qv_l, NTOK, E3, EDIM);
        attn_kernel<<<dim3(TSEQ / 64, NBATCH * NHEAD), 128, ATT_SMEM>>>(
            qv_h, qv_l, att_hi, att_lo);
        hmma_gemm_n<<<dim3(EDIM / 128, NTOK / 128), 256, NGEMM_SMEM>>>(
            att_hi, att_lo, wp_h + op, wp_l + op, proj_b + (size_t)l * EDIM,
            x, x, NTOK, EDIM, EDIM);

        ln_kernel<1><<<NTOK, 256>>>(x, lw, lb, nullptr, h_hi, h_lo, 1, 0);
        hmma_gemm_w<1><<<dim3(E4 / 256, NTOK / 128), 256, WGEMM_SMEM>>>(
            h_hi, h_lo, w1_h + o1, w1_l + o1, c1_b + (size_t)l * E4,
            nullptr, a1_hi, a1_lo, NTOK, E4, EDIM);
        hmma_gemm_n<<<dim3(EDIM / 128, NTOK / 128), 256, NGEMM_SMEM>>>(
            a1_hi, a1_lo, w2_h + o1, w2_l + o1, c2_b + (size_t)l * EDIM,
            x, x, NTOK, EDIM, E4);
    }

    ln_kernel<0><<<NBATCH, 256>>>(x, lnf_w, lnf_b, xf, nullptr, nullptr,
                                  TSEQ, TSEQ - 1);
    logits_kernel<<<VOCAB / 8, 256>>>(xf, wte, lm_b, out);
}

// round 14
// speedup vs baseline: 1.1349x; 1.0206x over previous
#include <cuda_runtime.h>
#include <cuda_bf16.h>
#include <math.h>
#include <stdint.h>

// ---------------------------------------------------------------------------
// GPT-2 small forward: B=8, T=1024, E=768, H=12, D=64, L=12, V=50304
// Round 14: round-10 base (best). Wide GEMM (128x256/64x64) ONLY for qkv
// (verified -10us/launch); narrow (128x128/64x32, 3-stage, frag dbl-buf)
// for proj/c1/c2. Attention = round-4 config. Fused cvt.
// ---------------------------------------------------------------------------

#define NTOK   8192
#define EDIM   768
#define E3     2304
#define E4     3072
#define NHEAD  12
#define HDIM   64
#define NLAYER 12
#define VOCAB  50304
#define NBATCH 8
#define TSEQ   1024

// ---------------- device scratch (allocation-free) ----------------
__device__ __align__(16) float          g_x    [NTOK * EDIM];
__device__ __align__(16) float          g_xf   [NBATCH * EDIM];
__device__ __align__(16) __nv_bfloat16  g_h_hi  [NTOK * EDIM];
__device__ __align__(16) __nv_bfloat16  g_h_lo  [NTOK * EDIM];
__device__ __align__(16) __nv_bfloat16  g_qkv_hi[NTOK * E3];
__device__ __align__(16) __nv_bfloat16  g_qkv_lo[NTOK * E3];
__device__ __align__(16) __nv_bfloat16  g_att_hi[NTOK * EDIM];
__device__ __align__(16) __nv_bfloat16  g_att_lo[NTOK * EDIM];
__device__ __align__(16) __nv_bfloat16  g_a1_hi [NTOK * E4];
__device__ __align__(16) __nv_bfloat16  g_a1_lo [NTOK * E4];
__device__ __align__(16) __nv_bfloat16  g_wqkv_hi[NLAYER * E3 * EDIM];
__device__ __align__(16) __nv_bfloat16  g_wqkv_lo[NLAYER * E3 * EDIM];
__device__ __align__(16) __nv_bfloat16  g_wprj_hi[NLAYER * EDIM * EDIM];
__device__ __align__(16) __nv_bfloat16  g_wprj_lo[NLAYER * EDIM * EDIM];
__device__ __align__(16) __nv_bfloat16  g_wc1_hi [NLAYER * E4 * EDIM];
__device__ __align__(16) __nv_bfloat16  g_wc1_lo [NLAYER * E4 * EDIM];
__device__ __align__(16) __nv_bfloat16  g_wc2_hi [NLAYER * EDIM * E4];
__device__ __align__(16) __nv_bfloat16  g_wc2_lo [NLAYER * EDIM * E4];

// ---------------- helpers ----------------
__device__ __forceinline__ uint32_t smem_u32(const void* p) {
    uint32_t a;
    asm("{ .reg .u64 t; cvta.to.shared.u64 t, %1; cvt.u32.u64 %0, t; }"
        : "=r"(a) : "l"(p));
    return a;
}
__device__ __forceinline__ void cpa16(uint32_t dst, const void* src) {
    asm volatile("cp.async.cg.shared.global [%0], [%1], 16;" :: "r"(dst), "l"(src));
}
__device__ __forceinline__ void cpa_commit() {
    asm volatile("cp.async.commit_group;" ::: "memory");
}
template<int N> __device__ __forceinline__ void cpa_wait() {
    asm volatile("cp.async.wait_group %0;" :: "n"(N) : "memory");
}
__device__ __forceinline__ void ldsm_x4(uint32_t* r, uint32_t a) {
    asm volatile("ldmatrix.sync.aligned.m8n8.x4.shared.b16 {%0,%1,%2,%3}, [%4];"
        : "=r"(r[0]), "=r"(r[1]), "=r"(r[2]), "=r"(r[3]) : "r"(a));
}
__device__ __forceinline__ void ldsm_x4p(uint32_t* r0, uint32_t* r1, uint32_t a) {
    asm volatile("ldmatrix.sync.aligned.m8n8.x4.shared.b16 {%0,%1,%2,%3}, [%4];"
        : "=r"(r0[0]), "=r"(r0[1]), "=r"(r1[0]), "=r"(r1[1]) : "r"(a));
}
__device__ __forceinline__ void ldsm_x2(uint32_t* r, uint32_t a) {
    asm volatile("ldmatrix.sync.aligned.m8n8.x2.shared.b16 {%0,%1}, [%2];"
        : "=r"(r[0]), "=r"(r[1]) : "r"(a));
}
__device__ __forceinline__ void ldsm_x2t(uint32_t* r, uint32_t a) {
    asm volatile("ldmatrix.sync.aligned.m8n8.x2.trans.shared.b16 {%0,%1}, [%2];"
        : "=r"(r[0]), "=r"(r[1]) : "r"(a));
}
__device__ __forceinline__ void mma_bf16(float* c, const uint32_t* a,
                                         const uint32_t* b) {
    asm volatile(
        "mma.sync.aligned.m16n8k16.row.col.f32.bf16.bf16.f32 "
        "{%0,%1,%2,%3}, {%4,%5,%6,%7}, {%8,%9}, {%0,%1,%2,%3};"
        : "+f"(c[0]), "+f"(c[1]), "+f"(c[2]), "+f"(c[3])
        : "r"(a[0]), "r"(a[1]), "r"(a[2]), "r"(a[3]), "r"(b[0]), "r"(b[1]));
}
__device__ __forceinline__ float gelu_exact(float v) {
    return 0.5f * v * (1.0f + erff(v * 0.70710678118654752f));
}

// ---------------------------------------------------------------------------
// Fused weight convert
// ---------------------------------------------------------------------------
__device__ __forceinline__ void cvt4(const float* w, __nv_bfloat16* hi,
                                     __nv_bfloat16* lo, int i) {
    float4 v = ((const float4*)w)[i];
    __nv_bfloat16 h0 = __float2bfloat16(v.x), h1 = __float2bfloat16(v.y);
    __nv_bfloat16 h2 = __float2bfloat16(v.z), h3 = __float2bfloat16(v.w);
    __nv_bfloat162 hh0, hh1, ll0, ll1;
    hh0.x = h0; hh0.y = h1; hh1.x = h2; hh1.y = h3;
    ll0.x = __float2bfloat16(v.x - __bfloat162float(h0));
    ll0.y = __float2bfloat16(v.y - __bfloat162float(h1));
    ll1.x = __float2bfloat16(v.z - __bfloat162float(h2));
    ll1.y = __float2bfloat16(v.w - __bfloat162float(h3));
    ((__nv_bfloat162*)hi)[i * 2 + 0] = hh0;
    ((__nv_bfloat162*)hi)[i * 2 + 1] = hh1;
    ((__nv_bfloat162*)lo)[i * 2 + 0] = ll0;
    ((__nv_bfloat162*)lo)[i * 2 + 1] = ll1;
}

#define NQ4 (NLAYER * E3 * EDIM / 4)
#define NP4 (NLAYER * EDIM * EDIM / 4)
#define N14 (NLAYER * E4 * EDIM / 4)

__global__ __launch_bounds__(256) void cvt_all_kernel(
    const float* __restrict__ wq, __nv_bfloat16* __restrict__ wqh,
    __nv_bfloat16* __restrict__ wql,
    const float* __restrict__ wp, __nv_bfloat16* __restrict__ wph,
    __nv_bfloat16* __restrict__ wpl,
    const float* __restrict__ w1, __nv_bfloat16* __restrict__ w1h,
    __nv_bfloat16* __restrict__ w1l,
    const float* __restrict__ w2, __nv_bfloat16* __restrict__ w2h,
    __nv_bfloat16* __restrict__ w2l)
{
    int i = blockIdx.x * 256 + threadIdx.x;
    if (i < NQ4) { cvt4(wq, wqh, wql, i); return; }
    i -= NQ4;
    if (i < NP4) { cvt4(wp, wph, wpl, i); return; }
    i -= NP4;
    if (i < N14) { cvt4(w1, w1h, w1l, i); return; }
    i -= N14;
    if (i < N14) { cvt4(w2, w2h, w2l, i); }
}
#define CVT_TOTAL (NQ4 + NP4 + 2 * N14)

// ---------------------------------------------------------------------------
// Embedding
// ---------------------------------------------------------------------------
__global__ __launch_bounds__(192) void embed_kernel(
    const int* __restrict__ idx, const float* __restrict__ wte,
    const float* __restrict__ wpe, float* __restrict__ x)
{
    const int n = blockIdx.x;
    const int t = n & (TSEQ - 1);
    const int tok = idx[n];
    const float4* pw = (const float4*)(wte + (size_t)tok * EDIM);
    const float4* pp = (const float4*)(wpe + (size_t)t * EDIM);
    float4* po = (float4*)(x + (size_t)n * EDIM);
    const int i = threadIdx.x;
    float4 a = pw[i], b = pp[i];
    po[i] = make_float4(a.x + b.x, a.y + b.y, a.z + b.z, a.w + b.w);
}

// ---------------------------------------------------------------------------
// LayerNorm.  OUTM=0 -> fp32 out; OUTM=1 -> bf16 hi/lo pair
// ---------------------------------------------------------------------------
template<int OUTM>
__global__ __launch_bounds__(256) void ln_kernel(
    const float* __restrict__ x, const float* __restrict__ w,
    const float* __restrict__ b, float* __restrict__ outf,
    __nv_bfloat16* __restrict__ outh, __nv_bfloat16* __restrict__ outl,
    int stride, int offset)
{
    __shared__ float red[8];
    const int row = blockIdx.x * stride + offset;
    const float* px = x + (size_t)row * EDIM;
    const int tid = threadIdx.x;

    float v0 = px[tid], v1 = px[tid + 256], v2 = px[tid + 512];
    float s = v0 + v1 + v2;
    #pragma unroll
    for (int o = 16; o; o >>= 1) s += __shfl_xor_sync(0xffffffffu, s, o);
    if ((tid & 31) == 0) red[tid >> 5] = s;
    __syncthreads();
    float tot = red[0]+red[1]+red[2]+red[3]+red[4]+red[5]+red[6]+red[7];
    const float mu = tot * (1.0f / EDIM);

    float d0 = v0 - mu, d1 = v1 - mu, d2 = v2 - mu;
    float q = d0*d0 + d1*d1 + d2*d2;
    #pragma unroll
    for (int o = 16; o; o >>= 1) q += __shfl_xor_sync(0xffffffffu, q, o);
    __syncthreads();
    if ((tid & 31) == 0) red[tid >> 5] = q;
    __syncthreads();
    float qt = red[0]+red[1]+red[2]+red[3]+red[4]+red[5]+red[6]+red[7];
    const float rstd = rsqrtf(qt * (1.0f / EDIM) + 1e-5f);

    const size_t ob = (size_t)blockIdx.x * EDIM;
    #pragma unroll
    for (int c = 0; c < 3; ++c) {
        const int col = tid + c * 256;
        const float dd = (c == 0 ? d0 : (c == 1 ? d1 : d2));
        float v = dd * rstd * w[col] + b[col];
        if (OUTM == 0) {
            outf[ob + col] = v;
        } else {
            __nv_bfloat16 h = __float2bfloat16(v);
            outh[ob + col] = h;
            outl[ob + col] = __float2bfloat16(v - __bfloat162float(h));
        }
    }
}

// ===========================================================================
// WIDE GEMM: 128x256 CTA, 8 warps, warp tile 64x64, BK=64, 2 stages x 96KB.
// qkv only (MODE 3: bias -> bf16 hi/lo).
// ===========================================================================
#define WSTG_BYTES 98304
#define WGEMM_SMEM (2 * WSTG_BYTES)

__device__ __forceinline__ void w_load_stage(
    uint32_t sbase,
    const __nv_bfloat16* __restrict__ Ah, const __nv_bfloat16* __restrict__ Al,
    const __nv_bfloat16* __restrict__ Bh, const __nv_bfloat16* __restrict__ Bl,
    int K, int k0, int tid)
{
    #pragma unroll
    for (int half = 0; half < 2; ++half) {
        const __nv_bfloat16* S = half ? Al : Ah;
        const uint32_t base = sbase + half * 16384;
        #pragma unroll
        for (int it = 0; it < 4; ++it) {
            const int i = tid + it * 256;
            const int row = i >> 3, c = i & 7;
            cpa16(base + (row << 7) + ((c ^ (row & 7)) << 4),
                  S + (size_t)row * K + k0 + c * 8);
        }
    }
    #pragma unroll
    for (int half = 0; half < 2; ++half) {
        const __nv_bfloat16* S = half ? Bl : Bh;
        const uint32_t base = sbase + 32768 + half * 32768;
        #pragma unroll
        for (int it = 0; it < 8; ++it) {
            const int i = tid + it * 256;
            const int row = i >> 3, c = i & 7;
            cpa16(base + (row << 7) + ((c ^ (row & 7)) << 4),
                  S + (size_t)row * K + k0 + c * 8);
        }
    }
    cpa_commit();
}

__global__ __launch_bounds__(256) void hmma_gemm_w(
    const __nv_bfloat16* __restrict__ Ah, const __nv_bfloat16* __restrict__ Al,
    const __nv_bfloat16* __restrict__ Bh, const __nv_bfloat16* __restrict__ Bl,
    const float* __restrict__ bias,
    __nv_bfloat16* __restrict__ Ch, __nv_bfloat16* __restrict__ Cl,
    int M, int N, int K)
{
    extern __shared__ char smem[];
    const uint32_t sb = smem_u32(smem);
    const int tid = threadIdx.x;
    const int wid = tid >> 5;
    const int lane = tid & 31;
    const int wm = wid >> 2;
    const int wn = wid & 3;
    const int bm = blockIdx.y * 128;
    const int bn = blockIdx.x * 256;

    const int nkk = K >> 6;

    Ah += (size_t)bm * K; Al += (size_t)bm * K;
    Bh += (size_t)bn * K; Bl += (size_t)bn * K;

    w_load_stage(sb, Ah, Al, Bh, Bl, K, 0, tid);
    w_load_stage(sb + WSTG_BYTES, Ah, Al, Bh, Bl, K, 64, tid);

    float acc[4][8][4];
    #pragma unroll
    for (int i = 0; i < 4; ++i)
        #pragma unroll
        for (int j = 0; j < 8; ++j)
            #pragma unroll
            for (int q = 0; q < 4; ++q) acc[i][j][q] = 0.0f;

    const int arow = wm * 64 + (lane & 15);
    const int akoff = (lane >> 4);
    const int brow = wn * 64 + (lane & 7) + ((lane >> 4) << 3);
    const int bkoff = ((lane >> 3) & 1);

    for (int kt = 0; kt < nkk; ++kt) {
        cpa_wait<1>();
        __syncthreads();

        const uint32_t sA  = sb + (uint32_t)(kt & 1) * WSTG_BYTES;
        const uint32_t sAl = sA + 16384;
        const uint32_t sBh = sA + 32768;
        const uint32_t sBl = sA + 65536;

        #pragma unroll
        for (int ks = 0; ks < 4; ++ks) {
            uint32_t afh[4][4], afl[4][4], bfh[8][2], bfl[8][2];
            const int kc = ks * 2 + akoff;
            #pragma unroll
            for (int mi = 0; mi < 4; ++mi) {
                const int r = arow + mi * 16;
                const uint32_t off = (r << 7) + ((kc ^ (r & 7)) << 4);
                ldsm_x4(afh[mi], sA + off);
                ldsm_x4(afl[mi], sAl + off);
            }
            const int kcb = ks * 2 + bkoff;
            #pragma unroll
            for (int p = 0; p < 4; ++p) {
                const int r = brow + p * 16;
                const uint32_t off = (r << 7) + ((kcb ^ (r & 7)) << 4);
                ldsm_x4p(bfh[p * 2], bfh[p * 2 + 1], sBh + off);
                ldsm_x4p(bfl[p * 2], bfl[p * 2 + 1], sBl + off);
            }
            #pragma unroll
            for (int ni = 0; ni < 8; ++ni)
                #pragma unroll
                for (int mi = 0; mi < 4; ++mi) {
                    mma_bf16(acc[mi][ni], afh[mi], bfh[ni]);
                    mma_bf16(acc[mi][ni], afh[mi], bfl[ni]);
                    mma_bf16(acc[mi][ni], afl[mi], bfh[ni]);
                }
        }

        __syncthreads();
        if (kt + 2 < nkk) {
            w_load_stage(sA, Ah, Al, Bh, Bl, K, (kt + 2) * 64, tid);
        } else {
            cpa_commit();
        }
    }

    const int grp = lane >> 2;
    const int tig = lane & 3;
    #pragma unroll
    for (int mi = 0; mi < 4; ++mi) {
        #pragma unroll
        for (int half = 0; half < 2; ++half) {
            const int grow = bm + wm * 64 + mi * 16 + grp + half * 8;
            #pragma unroll
            for (int ni = 0; ni < 8; ++ni) {
                const int gcol = bn + wn * 64 + ni * 8 + tig * 2;
                float v0 = acc[mi][ni][half * 2 + 0] + bias[gcol];
                float v1 = acc[mi][ni][half * 2 + 1] + bias[gcol + 1];
                __nv_bfloat16 h0 = __float2bfloat16(v0);
                __nv_bfloat16 h1 = __float2bfloat16(v1);
                __nv_bfloat162 hh, ll;
                hh.x = h0; hh.y = h1;
                ll.x = __float2bfloat16(v0 - __bfloat162float(h0));
                ll.y = __float2bfloat16(v1 - __bfloat162float(h1));
                *(__nv_bfloat162*)(Ch + (size_t)grow * N + gcol) = hh;
                *(__nv_bfloat162*)(Cl + (size_t)grow * N + gcol) = ll;
            }
        }
    }
}

// ===========================================================================
// NARROW GEMM (round-10): 128x128 CTA, 8 warps, warp tile 64x32, BK=64,
// 3 stages x 64KB, fragment double buffer.
// MODE: 1 bias+gelu->bf16 hi/lo   2 bias+residual->fp32
// ===========================================================================
#define NSTG_BYTES 65536
#define NGEMM_SMEM (3 * NSTG_BYTES)

__device__ __forceinline__ void n_load_stage(
    uint32_t sbase,
    const __nv_bfloat16* __restrict__ Ah, const __nv_bfloat16* __restrict__ Al,
    const __nv_bfloat16* __restrict__ Bh, const __nv_bfloat16* __restrict__ Bl,
    int K, int k0, int tid)
{
    const __nv_bfloat16* srcs[4] = { Ah, Al, Bh, Bl };
    #pragma unroll
    for (int t4 = 0; t4 < 4; ++t4) {
        const __nv_bfloat16* S = srcs[t4];
        const uint32_t base = sbase + t4 * 16384;
        #pragma unroll
        for (int it = 0; it < 4; ++it) {
            const int i = tid + it * 256;
            const int row = i >> 3, c = i & 7;
            cpa16(base + (row << 7) + ((c ^ (row & 7)) << 4),
                  S + (size_t)row * K + k0 + c * 8);
        }
    }
    cpa_commit();
}

template<int MODE>
__global__ __launch_bounds__(256, 1) void hmma_gemm_n(
    const __nv_bfloat16* __restrict__ Ah, const __nv_bfloat16* __restrict__ Al,
    const __nv_bfloat16* __restrict__ Bh, const __nv_bfloat16* __restrict__ Bl,
    const float* __restrict__ bias, const float* __restrict__ R,
    float* __restrict__ Cf, __nv_bfloat16* __restrict__ Ch,
    __nv_bfloat16* __restrict__ Cl, int M, int N, int K)
{
    extern __shared__ char smem[];
    const uint32_t sb = smem_u32(smem);
    const int tid = threadIdx.x;
    const int wid = tid >> 5;
    const int lane = tid & 31;
    const int wm = wid >> 2;
    const int wn = wid & 3;
    const int bm = blockIdx.y * 128;
    const int bn = blockIdx.x * 128;

    const int nkk = K >> 6;

    Ah += (size_t)bm * K; Al += (size_t)bm * K;
    Bh += (size_t)bn * K; Bl += (size_t)bn * K;

    n_load_stage(sb, Ah, Al, Bh, Bl, K, 0, tid);
    n_load_stage(sb + NSTG_BYTES, Ah, Al, Bh, Bl, K, 64, tid);

    float acc[4][4][4];
    #pragma unroll
    for (int i = 0; i < 4; ++i)
        #pragma unroll
        for (int j = 0; j < 4; ++j)
            #pragma unroll
            for (int q = 0; q < 4; ++q) acc[i][j][q] = 0.0f;

    const int arow = wm * 64 + (lane & 15);
    const int akoff = (lane >> 4);
    const int brow_base = wn * 32 + (lane & 7);
    const int bkoff = ((lane >> 3) & 1);

    uint32_t afh[2][4][4], afl[2][4][4], bfh[2][4][2], bfl[2][4][2];

    for (int kt = 0; kt < nkk; ++kt) {
        cpa_wait<1>();
        __syncthreads();

        if (kt + 2 < nkk) {
            n_load_stage(sb + (uint32_t)((kt + 2) % 3) * NSTG_BYTES,
                         Ah, Al, Bh, Bl, K, (kt + 2) * 64, tid);
        } else {
            cpa_commit();
        }

        const uint32_t sA  = sb + (uint32_t)(kt % 3) * NSTG_BYTES;
        const uint32_t sAl = sA + 16384;
        const uint32_t sBh = sA + 32768;
        const uint32_t sBl = sA + 49152;

        {
            const int kc = akoff;
            #pragma unroll
            for (int mi = 0; mi < 4; ++mi) {
                const int r = arow + mi * 16;
                const uint32_t off = (r << 7) + ((kc ^ (r & 7)) << 4);
                ldsm_x4(afh[0][mi], sA + off);
                ldsm_x4(afl[0][mi], sAl + off);
            }
            const int kcb = bkoff;
            #pragma unroll
            for (int ni = 0; ni < 4; ++ni) {
                const int r = brow_base + ni * 8;
                const uint32_t off = (r << 7) + ((kcb ^ (r & 7)) << 4);
                ldsm_x2(bfh[0][ni], sBh + off);
                ldsm_x2(bfl[0][ni], sBl + off);
            }
        }

        #pragma unroll
        for (int ks = 0; ks < 4; ++ks) {
            const int cur = ks & 1;
            if (ks < 3) {
                const int nxt = cur ^ 1;
                const int kc = (ks + 1) * 2 + akoff;
                #pragma unroll
                for (int mi = 0; mi < 4; ++mi) {
                    const int r = arow + mi * 16;
                    const uint32_t off = (r << 7) + ((kc ^ (r & 7)) << 4);
                    ldsm_x4(afh[nxt][mi], sA + off);
                    ldsm_x4(afl[nxt][mi], sAl + off);
                }
                const int kcb = (ks + 1) * 2 + bkoff;
                #pragma unroll
                for (int ni = 0; ni < 4; ++ni) {
                    const int r = brow_base + ni * 8;
                    const uint32_t off = (r << 7) + ((kcb ^ (r & 7)) << 4);
                    ldsm_x2(bfh[nxt][ni], sBh + off);
                    ldsm_x2(bfl[nxt][ni], sBl + off);
                }
            }
            #pragma unroll
            for (int ni = 0; ni < 4; ++ni)
                #pragma unroll
                for (int mi = 0; mi < 4; ++mi) {
                    mma_bf16(acc[mi][ni], afh[cur][mi], bfh[cur][ni]);
                    mma_bf16(acc[mi][ni], afh[cur][mi], bfl[cur][ni]);
                    mma_bf16(acc[mi][ni], afl[cur][mi], bfh[cur][ni]);
                }
        }
    }

    const int grp = lane >> 2;
    const int tig = lane & 3;
    #pragma unroll
    for (int mi = 0; mi < 4; ++mi) {
        #pragma unroll
        for (int half = 0; half < 2; ++half) {
            const int grow = bm + wm * 64 + mi * 16 + grp + half * 8;
            #pragma unroll
            for (int ni = 0; ni < 4; ++ni) {
                const int gcol = bn + wn * 32 + ni * 8 + tig * 2;
                float v0 = acc[mi][ni][half * 2 + 0] + bias[gcol];
                float v1 = acc[mi][ni][half * 2 + 1] + bias[gcol + 1];
                if (MODE == 2) {
                    float2 rr = *(const float2*)(R + (size_t)grow * N + gcol);
                    *(float2*)(Cf + (size_t)grow * N + gcol) =
                        make_float2(v0 + rr.x, v1 + rr.y);
                } else {
                    v0 = gelu_exact(v0); v1 = gelu_exact(v1);
                    __nv_bfloat16 h0 = __float2bfloat16(v0);
                    __nv_bfloat16 h1 = __float2bfloat16(v1);
                    __nv_bfloat162 hh, ll;
                    hh.x = h0; hh.y = h1;
                    ll.x = __float2bfloat16(v0 - __bfloat162float(h0));
                    ll.y = __float2bfloat16(v1 - __bfloat162float(h1));
                    *(__nv_bfloat162*)(Ch + (size_t)grow * N + gcol) = hh;
                    *(__nv_bfloat162*)(Cl + (size_t)grow * N + gcol) = ll;
                }
            }
        }
    }
}

// ---------------------------------------------------------------------------
// HMMA flash attention (round-4 double-buffered config). Heavy q-tiles first.
// ---------------------------------------------------------------------------
#define ATT_SMEM (16384 + 2 * 32768)

__device__ __forceinline__ void attn_stage_load(
    uint32_t sbase, const __nv_bfloat16* __restrict__ qh,
    const __nv_bfloat16* __restrict__ ql, int growbase, int colbase, int tid)
{
    #pragma unroll
    for (int it = 0; it < 16; ++it) {
        const int i = tid + it * 128;
        const int tile = i >> 9;
        const int r = (i >> 3) & 63;
        const int c = i & 7;
        const __nv_bfloat16* arr = (tile & 1) ? ql : qh;
        const int seg = (tile >> 1) ? 2 * EDIM : 0;
        cpa16(sbase + tile * 8192 + (r << 7) + ((c ^ (r & 7)) << 4),
              arr + (size_t)(growbase + r) * E3 + seg + colbase + c * 8);
    }
}

__global__ __launch_bounds__(128, 2) void attn_kernel(
    const __nv_bfloat16* __restrict__ qh, const __nv_bfloat16* __restrict__ ql,
    __nv_bfloat16* __restrict__ yh, __nv_bfloat16* __restrict__ yl)
{
    extern __shared__ char smem[];
    const uint32_t sb = smem_u32(smem);
    const int tid = threadIdx.x;
    const int w = tid >> 5;
    const int lane = tid & 31;
    const int qt = gridDim.x - 1 - blockIdx.x;
    const int bh = blockIdx.y;
    const int b = bh / NHEAD;
    const int hh = bh % NHEAD;
    const int colbase = hh * HDIM;
    const int qrowbase = b * TSEQ + qt * 64;

    #pragma unroll
    for (int it = 0; it < 8; ++it) {
        const int i = tid + it * 128;
        const int tile = i >> 9;
        const int r = (i >> 3) & 63;
        const int c = i & 7;
        const __nv_bfloat16* arr = tile ? ql : qh;
        cpa16(sb + tile * 8192 + (r << 7) + ((c ^ (r & 7)) << 4),
              arr + (size_t)(qrowbase + r) * E3 + EDIM + colbase + c * 8);
    }
    attn_stage_load(sb + 16384, qh, ql, b * TSEQ, colbase, tid);
    cpa_commit();

    uint32_t qfh[4][4], qfl[4][4];
    float o[8][4];
    #pragma unroll
    for (int ni = 0; ni < 8; ++ni)
        #pragma unroll
        for (int q = 0; q < 4; ++q) o[ni][q] = 0.0f;
    float m0 = -1e30f, m1 = -1e30f, l0 = 0.0f, l1 = 0.0f;

    const uint32_t stg[2] = { sb + 16384, sb + 16384 + 32768 };
    const int rl0 = w * 16 + (lane >> 2);
    const int cl0 = (lane & 3) * 2;

    for (int kt = 0; kt <= qt; ++kt) {
        if (kt + 1 <= qt)
            attn_stage_load(stg[(kt + 1) & 1], qh, ql,
                            b * TSEQ + (kt + 1) * 64, colbase, tid);
        cpa_commit();
        cpa_wait<1>();
        __syncthreads();

        if (kt == 0) {
            const int r = w * 16 + (lane & 15);
            #pragma unroll
            for (int ks = 0; ks < 4; ++ks) {
                const int kc = ks * 2 + (lane >> 4);
                const uint32_t off = (r << 7) + ((kc ^ (r & 7)) << 4);
                ldsm_x4(qfh[ks], sb + off);
                ldsm_x4(qfl[ks], sb + 8192 + off);
            }
        }

        const uint32_t sKh = stg[kt & 1];
        const uint32_t sKl = sKh + 8192;
        const uint32_t sVh = sKh + 16384;
        const uint32_t sVl = sKh + 24576;

        float s[8][4];
        #pragma unroll
        for (int ni = 0; ni < 8; ++ni)
            #pragma unroll
            for (int q = 0; q < 4; ++q) s[ni][q] = 0.0f;

        #pragma unroll
        for (int ks = 0; ks < 4; ++ks) {
            const int kcb = ks * 2 + ((lane >> 3) & 1);
            #pragma unroll
            for (int ni = 0; ni < 8; ++ni) {
                const int r = ni * 8 + (lane & 7);
                const uint32_t off = (r << 7) + ((kcb ^ (r & 7)) << 4);
                uint32_t kfh[2], kfl[2];
                ldsm_x2(kfh, sKh + off);
                ldsm_x2(kfl, sKl + off);
                mma_bf16(s[ni], qfh[ks], kfh);
                mma_bf16(s[ni], qfh[ks], kfl);
                mma_bf16(s[ni], qfl[ks], kfh);
            }
        }

        if (kt == qt) {
            #pragma unroll
            for (int ni = 0; ni < 8; ++ni) {
                const int c0 = ni * 8 + cl0;
                if (c0 > rl0)     s[ni][0] = -1e30f;
                if (c0 + 1 > rl0) s[ni][1] = -1e30f;
                if (c0 > rl0 + 8)     s[ni][2] = -1e30f;
                if (c0 + 1 > rl0 + 8) s[ni][3] = -1e30f;
            }
        }

        float mx0 = -1e30f, mx1 = -1e30f;
        #pragma unroll
        for (int ni = 0; ni < 8; ++ni) {
            mx0 = fmaxf(mx0, fmaxf(s[ni][0], s[ni][1]));
            mx1 = fmaxf(mx1, fmaxf(s[ni][2], s[ni][3]));
        }
        mx0 = fmaxf(mx0, __shfl_xor_sync(0xffffffffu, mx0, 1, 4));
        mx0 = fmaxf(mx0, __shfl_xor_sync(0xffffffffu, mx0, 2, 4));
        mx1 = fmaxf(mx1, __shfl_xor_sync(0xffffffffu, mx1, 1, 4));
        mx1 = fmaxf(mx1, __shfl_xor_sync(0xffffffffu, mx1, 2, 4));
        const float nm0 = fmaxf(m0, mx0), nm1 = fmaxf(m1, mx1);
        const float al0 = __expf(m0 - nm0), al1 = __expf(m1 - nm1);
        float rs0 = 0.0f, rs1 = 0.0f;
        #pragma unroll
        for (int ni = 0; ni < 8; ++ni) {
            s[ni][0] = __expf(s[ni][0] - nm0); rs0 += s[ni][0];
            s[ni][1] = __expf(s[ni][1] - nm0); rs0 += s[ni][1];
            s[ni][2] = __expf(s[ni][2] - nm1); rs1 += s[ni][2];
            s[ni][3] = __expf(s[ni][3] - nm1); rs1 += s[ni][3];
        }
        rs0 += __shfl_xor_sync(0xffffffffu, rs0, 1, 4);
        rs0 += __shfl_xor_sync(0xffffffffu, rs0, 2, 4);
        rs1 += __shfl_xor_sync(0xffffffffu, rs1, 1, 4);
        rs1 += __shfl_xor_sync(0xffffffffu, rs1, 2, 4);
        l0 = l0 * al0 + rs0; m0 = nm0;
        l1 = l1 * al1 + rs1; m1 = nm1;
        #pragma unroll
        for (int ni = 0; ni < 8; ++ni) {
            o[ni][0] *= al0; o[ni][1] *= al0;
            o[ni][2] *= al1; o[ni][3] *= al1;
        }

        uint32_t pah[4][4], pal[4][4];
        #pragma unroll
        for (int kc = 0; kc < 4; ++kc) {
            #pragma unroll
            for (int half = 0; half < 2; ++half) {
                const int ni = kc * 2 + half;
                #pragma unroll
                for (int pr = 0; pr < 2; ++pr) {
                    float p0 = s[ni][pr * 2 + 0];
                    float p1 = s[ni][pr * 2 + 1];
                    __nv_bfloat16 h0 = __float2bfloat16(p0);
                    __nv_bfloat16 h1 = __float2bfloat16(p1);
                    __nv_bfloat162 hh, ll;
                    hh.x = h0; hh.y = h1;
                    ll.x = __float2bfloat16(p0 - __bfloat162float(h0));
                    ll.y = __float2bfloat16(p1 - __bfloat162float(h1));
                    pah[kc][half * 2 + pr] = *(uint32_t*)&hh;
                    pal[kc][half * 2 + pr] = *(uint32_t*)&ll;
                }
            }
        }

        #pragma unroll
        for (int kc = 0; kc < 4; ++kc) {
            const int rV = kc * 16 + (lane & 15);
            #pragma unroll
            for (int ni = 0; ni < 8; ++ni) {
                const uint32_t off = (rV << 7) + ((ni ^ (rV & 7)) << 4);
                uint32_t vfh[2], vfl[2];
                ldsm_x2t(vfh, sVh + off);
                ldsm_x2t(vfl, sVl + off);
                mma_bf16(o[ni], pah[kc], vfh);
                mma_bf16(o[ni], pah[kc], vfl);
                mma_bf16(o[ni], pal[kc], vfh);
            }
        }
        __syncthreads();
    }

    const float il0 = 1.0f / l0, il1 = 1.0f / l1;
    const size_t row0 = (size_t)(qrowbase + rl0) * EDIM + colbase + cl0;
    const size_t row1 = (size_t)(qrowbase + rl0 + 8) * EDIM + colbase + cl0;
    #pragma unroll
    for (int ni = 0; ni < 8; ++ni) {
        const int dc = ni * 8;
        float v0 = o[ni][0] * il0, v1 = o[ni][1] * il0;
        float v2 = o[ni][2] * il1, v3 = o[ni][3] * il1;
        __nv_bfloat16 h0 = __float2bfloat16(v0), h1 = __float2bfloat16(v1);
        __nv_bfloat16 h2 = __float2bfloat16(v2), h3 = __float2bfloat16(v3);
        __nv_bfloat162 a, bb, c, d;
        a.x = h0; a.y = h1; c.x = h2; c.y = h3;
        bb.x = __float2bfloat16(v0 - __bfloat162float(h0));
        bb.y = __float2bfloat16(v1 - __bfloat162float(h1));
        d.x = __float2bfloat16(v2 - __bfloat162float(h2));
        d.y = __float2bfloat16(v3 - __bfloat162float(h3));
        *(__nv_bfloat162*)(yh + row0 + dc) = a;
        *(__nv_bfloat162*)(yl + row0 + dc) = bb;
        *(__nv_bfloat162*)(yh + row1 + dc) = c;
        *(__nv_bfloat162*)(yl + row1 + dc) = d;
    }
}

// ---------------------------------------------------------------------------
// lm_head
// ---------------------------------------------------------------------------
__global__ __launch_bounds__(256) void logits_kernel(
    const float* __restrict__ xf, const float* __restrict__ wte,
    const float* __restrict__ lm_b, float* __restrict__ out)
{
    __shared__ float xs[NBATCH * EDIM];
    for (int i = threadIdx.x; i < NBATCH * EDIM; i += 256) xs[i] = xf[i];
    __syncthreads();

    const int warp = threadIdx.x >> 5;
    const int lane = threadIdx.x & 31;
    const int v = blockIdx.x * 8 + warp;

    const float* wrow = wte + (size_t)v * EDIM;
    float acc[NBATCH];
    #pragma unroll
    for (int b = 0; b < NBATCH; ++b) acc[b] = 0.0f;

    for (int k4 = lane * 4; k4 < EDIM; k4 += 128) {
        float4 wv = *(const float4*)(wrow + k4);
        #pragma unroll
        for (int b = 0; b < NBATCH; ++b) {
            float4 xv = *(const float4*)(xs + b * EDIM + k4);
            acc[b] += wv.x*xv.x + wv.y*xv.y + wv.z*xv.z + wv.w*xv.w;
        }
    }
    #pragma unroll
    for (int o = 16; o; o >>= 1)
        #pragma unroll
        for (int b = 0; b < NBATCH; ++b)
            acc[b] += __shfl_xor_sync(0xffffffffu, acc[b], o);

    if (lane == 0) {
        const float bb = lm_b[v];
        #pragma unroll
        for (int b = 0; b < NBATCH; ++b)
            out[(size_t)b * VOCAB + v] = acc[b] + bb;
    }
}

// ---------------------------------------------------------------------------
// Launcher
// ---------------------------------------------------------------------------
extern "C" void kernel_launch(void* const* d_in, const int* in_sizes, int n_in,
                              void* d_out, int out_size)
{
    (void)in_sizes; (void)n_in; (void)out_size;
    const int*   idx    = (const int*)  d_in[0];
    const float* wte    = (const float*)d_in[1];
    const float* wpe    = (const float*)d_in[2];
    const float* qkv_w  = (const float*)d_in[3];
    const float* qkv_b  = (const float*)d_in[4];
    const float* proj_w = (const float*)d_in[5];
    const float* proj_b = (const float*)d_in[6];
    const float* ln_w   = (const float*)d_in[7];
    const float* ln_b   = (const float*)d_in[8];
    const float* c1_w   = (const float*)d_in[9];
    const float* c1_b   = (const float*)d_in[10];
    const float* c2_w   = (const float*)d_in[11];
    const float* c2_b   = (const float*)d_in[12];
    const float* lnf_w  = (const float*)d_in[13];
    const float* lnf_b  = (const float*)d_in[14];
    const float* lm_b   = (const float*)d_in[15];
    float* out = (float*)d_out;

    float *x, *xf;
    __nv_bfloat16 *h_hi, *h_lo, *qv_h, *qv_l, *att_hi, *att_lo, *a1_hi, *a1_lo;
    __nv_bfloat16 *wq_h, *wq_l, *wp_h, *wp_l, *w1_h, *w1_l, *w2_h, *w2_l;
    cudaGetSymbolAddress((void**)&x,     g_x);
    cudaGetSymbolAddress((void**)&xf,    g_xf);
    cudaGetSymbolAddress((void**)&h_hi,  g_h_hi);
    cudaGetSymbolAddress((void**)&h_lo,  g_h_lo);
    cudaGetSymbolAddress((void**)&qv_h,  g_qkv_hi);
    cudaGetSymbolAddress((void**)&qv_l,  g_qkv_lo);
    cudaGetSymbolAddress((void**)&att_hi,g_att_hi);
    cudaGetSymbolAddress((void**)&att_lo,g_att_lo);
    cudaGetSymbolAddress((void**)&a1_hi, g_a1_hi);
    cudaGetSymbolAddress((void**)&a1_lo, g_a1_lo);
    cudaGetSymbolAddress((void**)&wq_h,  g_wqkv_hi);
    cudaGetSymbolAddress((void**)&wq_l,  g_wqkv_lo);
    cudaGetSymbolAddress((void**)&wp_h,  g_wprj_hi);
    cudaGetSymbolAddress((void**)&wp_l,  g_wprj_lo);
    cudaGetSymbolAddress((void**)&w1_h,  g_wc1_hi);
    cudaGetSymbolAddress((void**)&w1_l,  g_wc1_lo);
    cudaGetSymbolAddress((void**)&w2_h,  g_wc2_hi);
    cudaGetSymbolAddress((void**)&w2_l,  g_wc2_lo);

    cudaFuncSetAttribute(attn_kernel,
        cudaFuncAttributeMaxDynamicSharedMemorySize, ATT_SMEM);
    cudaFuncSetAttribute(hmma_gemm_w,
        cudaFuncAttributeMaxDynamicSharedMemorySize, WGEMM_SMEM);
    cudaFuncSetAttribute(hmma_gemm_n<1>,
        cudaFuncAttributeMaxDynamicSharedMemorySize, NGEMM_SMEM);
    cudaFuncSetAttribute(hmma_gemm_n<2>,
        cudaFuncAttributeMaxDynamicSharedMemorySize, NGEMM_SMEM);

    cvt_all_kernel<<<(CVT_TOTAL + 255) / 256, 256>>>(
        qkv_w, wq_h, wq_l, proj_w, wp_h, wp_l,
        c1_w, w1_h, w1_l, c2_w, w2_h, w2_l);

    embed_kernel<<<NTOK, 192>>>(idx, wte, wpe, x);

    for (int l = 0; l < NLAYER; ++l) {
        const float* lw = ln_w + l * EDIM;
        const float* lb = ln_b + l * EDIM;
        const size_t oq = (size_t)l * E3 * EDIM;
        const size_t op = (size_t)l * EDIM * EDIM;
        const size_t o1 = (size_t)l * E4 * EDIM;

        ln_kernel<1><<<NTOK, 256>>>(x, lw, lb, nullptr, h_hi, h_lo, 1, 0);
        hmma_gemm_w<<<dim3(E3 / 256, NTOK / 128), 256, WGEMM_SMEM>>>(
            h_hi, h_lo, wq_h + oq, wq_l + oq, qkv_b + (size_t)l * E3,
            qv_h, qv_l, NTOK, E3, EDIM);
        attn_kernel<<<dim3(TSEQ / 64, NBATCH * NHEAD), 128, ATT_SMEM>>>(
            qv_h, qv_l, att_hi, att_lo);
        hmma_gemm_n<2><<<dim3(EDIM / 128, NTOK / 128), 256, NGEMM_SMEM>>>(
            att_hi, att_lo, wp_h + op, wp_l + op, proj_b + (size_t)l * EDIM,
            x, x, nullptr, nullptr, NTOK, EDIM, EDIM);

        ln_kernel<1><<<NTOK, 256>>>(x, lw, lb, nullptr, h_hi, h_lo, 1, 0);
        hmma_gemm_n<1><<<dim3(E4 / 128, NTOK / 128), 256, NGEMM_SMEM>>>(
            h_hi, h_lo, w1_h + o1, w1_l + o1, c1_b + (size_t)l * E4,
            nullptr, nullptr, a1_hi, a1_lo, NTOK, E4, EDIM);
        hmma_gemm_n<2><<<dim3(EDIM / 128, NTOK / 128), 256, NGEMM_SMEM>>>(
            a1_hi, a1_lo, w2_h + o1, w2_l + o1, c2_b + (size_t)l * EDIM,
            x, x, nullptr, nullptr, NTOK, EDIM, E4);
    }

    ln_kernel<0><<<NBATCH, 256>>>(x, lnf_w, lnf_b, xf, nullptr, nullptr,
                                  TSEQ, TSEQ - 1);
    logits_kernel<<<VOCAB / 8, 256>>>(xf, wte, lm_b, out);
}

// round 15
// speedup vs baseline: 1.1397x; 1.0042x over previous
#include <cuda_runtime.h>
#include <cuda_bf16.h>
#include <math.h>
#include <stdint.h>

// ---------------------------------------------------------------------------
// GPT-2 small forward: B=8, T=1024, E=768, H=12, D=64, L=12, V=50304
// Round 15: round-14 base (best, 13029us). Vectorized 192-thread LayerNorm
// (float4 loads, bfloat162 stores). All GEMM/attention kernels unchanged.
// ---------------------------------------------------------------------------

#define NTOK   8192
#define EDIM   768
#define E3     2304
#define E4     3072
#define NHEAD  12
#define HDIM   64
#define NLAYER 12
#define VOCAB  50304
#define NBATCH 8
#define TSEQ   1024

// ---------------- device scratch (allocation-free) ----------------
__device__ __align__(16) float          g_x    [NTOK * EDIM];
__device__ __align__(16) float          g_xf   [NBATCH * EDIM];
__device__ __align__(16) __nv_bfloat16  g_h_hi  [NTOK * EDIM];
__device__ __align__(16) __nv_bfloat16  g_h_lo  [NTOK * EDIM];
__device__ __align__(16) __nv_bfloat16  g_qkv_hi[NTOK * E3];
__device__ __align__(16) __nv_bfloat16  g_qkv_lo[NTOK * E3];
__device__ __align__(16) __nv_bfloat16  g_att_hi[NTOK * EDIM];
__device__ __align__(16) __nv_bfloat16  g_att_lo[NTOK * EDIM];
__device__ __align__(16) __nv_bfloat16  g_a1_hi [NTOK * E4];
__device__ __align__(16) __nv_bfloat16  g_a1_lo [NTOK * E4];
__device__ __align__(16) __nv_bfloat16  g_wqkv_hi[NLAYER * E3 * EDIM];
__device__ __align__(16) __nv_bfloat16  g_wqkv_lo[NLAYER * E3 * EDIM];
__device__ __align__(16) __nv_bfloat16  g_wprj_hi[NLAYER * EDIM * EDIM];
__device__ __align__(16) __nv_bfloat16  g_wprj_lo[NLAYER * EDIM * EDIM];
__device__ __align__(16) __nv_bfloat16  g_wc1_hi [NLAYER * E4 * EDIM];
__device__ __align__(16) __nv_bfloat16  g_wc1_lo [NLAYER * E4 * EDIM];
__device__ __align__(16) __nv_bfloat16  g_wc2_hi [NLAYER * EDIM * E4];
__device__ __align__(16) __nv_bfloat16  g_wc2_lo [NLAYER * EDIM * E4];

// ---------------- helpers ----------------
__device__ __forceinline__ uint32_t smem_u32(const void* p) {
    uint32_t a;
    asm("{ .reg .u64 t; cvta.to.shared.u64 t, %1; cvt.u32.u64 %0, t; }"
        : "=r"(a) : "l"(p));
    return a;
}
__device__ __forceinline__ void cpa16(uint32_t dst, const void* src) {
    asm volatile("cp.async.cg.shared.global [%0], [%1], 16;" :: "r"(dst), "l"(src));
}
__device__ __forceinline__ void cpa_commit() {
    asm volatile("cp.async.commit_group;" ::: "memory");
}
template<int N> __device__ __forceinline__ void cpa_wait() {
    asm volatile("cp.async.wait_group %0;" :: "n"(N) : "memory");
}
__device__ __forceinline__ void ldsm_x4(uint32_t* r, uint32_t a) {
    asm volatile("ldmatrix.sync.aligned.m8n8.x4.shared.b16 {%0,%1,%2,%3}, [%4];"
        : "=r"(r[0]), "=r"(r[1]), "=r"(r[2]), "=r"(r[3]) : "r"(a));
}
__device__ __forceinline__ void ldsm_x4p(uint32_t* r0, uint32_t* r1, uint32_t a) {
    asm volatile("ldmatrix.sync.aligned.m8n8.x4.shared.b16 {%0,%1,%2,%3}, [%4];"
        : "=r"(r0[0]), "=r"(r0[1]), "=r"(r1[0]), "=r"(r1[1]) : "r"(a));
}
__device__ __forceinline__ void ldsm_x2(uint32_t* r, uint32_t a) {
    asm volatile("ldmatrix.sync.aligned.m8n8.x2.shared.b16 {%0,%1}, [%2];"
        : "=r"(r[0]), "=r"(r[1]) : "r"(a));
}
__device__ __forceinline__ void ldsm_x2t(uint32_t* r, uint32_t a) {
    asm volatile("ldmatrix.sync.aligned.m8n8.x2.trans.shared.b16 {%0,%1}, [%2];"
        : "=r"(r[0]), "=r"(r[1]) : "r"(a));
}
__device__ __forceinline__ void mma_bf16(float* c, const uint32_t* a,
                                         const uint32_t* b) {
    asm volatile(
        "mma.sync.aligned.m16n8k16.row.col.f32.bf16.bf16.f32 "
        "{%0,%1,%2,%3}, {%4,%5,%6,%7}, {%8,%9}, {%0,%1,%2,%3};"
        : "+f"(c[0]), "+f"(c[1]), "+f"(c[2]), "+f"(c[3])
        : "r"(a[0]), "r"(a[1]), "r"(a[2]), "r"(a[3]), "r"(b[0]), "r"(b[1]));
}
__device__ __forceinline__ float gelu_exact(float v) {
    return 0.5f * v * (1.0f + erff(v * 0.70710678118654752f));
}

// ---------------------------------------------------------------------------
// Fused weight convert
// ---------------------------------------------------------------------------
__device__ __forceinline__ void cvt4(const float* w, __nv_bfloat16* hi,
                                     __nv_bfloat16* lo, int i) {
    float4 v = ((const float4*)w)[i];
    __nv_bfloat16 h0 = __float2bfloat16(v.x), h1 = __float2bfloat16(v.y);
    __nv_bfloat16 h2 = __float2bfloat16(v.z), h3 = __float2bfloat16(v.w);
    __nv_bfloat162 hh0, hh1, ll0, ll1;
    hh0.x = h0; hh0.y = h1; hh1.x = h2; hh1.y = h3;
    ll0.x = __float2bfloat16(v.x - __bfloat162float(h0));
    ll0.y = __float2bfloat16(v.y - __bfloat162float(h1));
    ll1.x = __float2bfloat16(v.z - __bfloat162float(h2));
    ll1.y = __float2bfloat16(v.w - __bfloat162float(h3));
    ((__nv_bfloat162*)hi)[i * 2 + 0] = hh0;
    ((__nv_bfloat162*)hi)[i * 2 + 1] = hh1;
    ((__nv_bfloat162*)lo)[i * 2 + 0] = ll0;
    ((__nv_bfloat162*)lo)[i * 2 + 1] = ll1;
}

#define NQ4 (NLAYER * E3 * EDIM / 4)
#define NP4 (NLAYER * EDIM * EDIM / 4)
#define N14 (NLAYER * E4 * EDIM / 4)

__global__ __launch_bounds__(256) void cvt_all_kernel(
    const float* __restrict__ wq, __nv_bfloat16* __restrict__ wqh,
    __nv_bfloat16* __restrict__ wql,
    const float* __restrict__ wp, __nv_bfloat16* __restrict__ wph,
    __nv_bfloat16* __restrict__ wpl,
    const float* __restrict__ w1, __nv_bfloat16* __restrict__ w1h,
    __nv_bfloat16* __restrict__ w1l,
    const float* __restrict__ w2, __nv_bfloat16* __restrict__ w2h,
    __nv_bfloat16* __restrict__ w2l)
{
    int i = blockIdx.x * 256 + threadIdx.x;
    if (i < NQ4) { cvt4(wq, wqh, wql, i); return; }
    i -= NQ4;
    if (i < NP4) { cvt4(wp, wph, wpl, i); return; }
    i -= NP4;
    if (i < N14) { cvt4(w1, w1h, w1l, i); return; }
    i -= N14;
    if (i < N14) { cvt4(w2, w2h, w2l, i); }
}
#define CVT_TOTAL (NQ4 + NP4 + 2 * N14)

// ---------------------------------------------------------------------------
// Embedding
// ---------------------------------------------------------------------------
__global__ __launch_bounds__(192) void embed_kernel(
    const int* __restrict__ idx, const float* __restrict__ wte,
    const float* __restrict__ wpe, float* __restrict__ x)
{
    const int n = blockIdx.x;
    const int t = n & (TSEQ - 1);
    const int tok = idx[n];
    const float4* pw = (const float4*)(wte + (size_t)tok * EDIM);
    const float4* pp = (const float4*)(wpe + (size_t)t * EDIM);
    float4* po = (float4*)(x + (size_t)n * EDIM);
    const int i = threadIdx.x;
    float4 a = pw[i], b = pp[i];
    po[i] = make_float4(a.x + b.x, a.y + b.y, a.z + b.z, a.w + b.w);
}

// ---------------------------------------------------------------------------
// LayerNorm, 192 threads, fully vectorized (float4 in, float4/bf162 out).
// OUTM=0 -> fp32 out; OUTM=1 -> bf16 hi/lo pair.
// ---------------------------------------------------------------------------
template<int OUTM>
__global__ __launch_bounds__(192) void ln_kernel(
    const float* __restrict__ x, const float* __restrict__ w,
    const float* __restrict__ b, float* __restrict__ outf,
    __nv_bfloat16* __restrict__ outh, __nv_bfloat16* __restrict__ outl,
    int stride, int offset)
{
    __shared__ float red[6];
    const int row = blockIdx.x * stride + offset;
    const int tid = threadIdx.x;
    const float4 v = *(const float4*)(x + (size_t)row * EDIM + tid * 4);

    float s = v.x + v.y + v.z + v.w;
    #pragma unroll
    for (int o = 16; o; o >>= 1) s += __shfl_xor_sync(0xffffffffu, s, o);
    if ((tid & 31) == 0) red[tid >> 5] = s;
    __syncthreads();
    const float mu = (red[0]+red[1]+red[2]+red[3]+red[4]+red[5]) * (1.0f/EDIM);

    const float d0 = v.x - mu, d1 = v.y - mu, d2 = v.z - mu, d3 = v.w - mu;
    float q = d0*d0 + d1*d1 + d2*d2 + d3*d3;
    #pragma unroll
    for (int o = 16; o; o >>= 1) q += __shfl_xor_sync(0xffffffffu, q, o);
    __syncthreads();
    if ((tid & 31) == 0) red[tid >> 5] = q;
    __syncthreads();
    const float var = (red[0]+red[1]+red[2]+red[3]+red[4]+red[5]) * (1.0f/EDIM);
    const float rstd = rsqrtf(var + 1e-5f);

    const float4 wv = *(const float4*)(w + tid * 4);
    const float4 bv = *(const float4*)(b + tid * 4);
    const float r0 = d0 * rstd * wv.x + bv.x;
    const float r1 = d1 * rstd * wv.y + bv.y;
    const float r2 = d2 * rstd * wv.z + bv.z;
    const float r3 = d3 * rstd * wv.w + bv.w;

    const size_t ob = (size_t)blockIdx.x * EDIM + tid * 4;
    if (OUTM == 0) {
        *(float4*)(outf + ob) = make_float4(r0, r1, r2, r3);
    } else {
        __nv_bfloat16 h0 = __float2bfloat16(r0), h1 = __float2bfloat16(r1);
        __nv_bfloat16 h2 = __float2bfloat16(r2), h3 = __float2bfloat16(r3);
        __nv_bfloat162 hh0, hh1, ll0, ll1;
        hh0.x = h0; hh0.y = h1; hh1.x = h2; hh1.y = h3;
        ll0.x = __float2bfloat16(r0 - __bfloat162float(h0));
        ll0.y = __float2bfloat16(r1 - __bfloat162float(h1));
        ll1.x = __float2bfloat16(r2 - __bfloat162float(h2));
        ll1.y = __float2bfloat16(r3 - __bfloat162float(h3));
        *(__nv_bfloat162*)(outh + ob)     = hh0;
        *(__nv_bfloat162*)(outh + ob + 2) = hh1;
        *(__nv_bfloat162*)(outl + ob)     = ll0;
        *(__nv_bfloat162*)(outl + ob + 2) = ll1;
    }
}

// ===========================================================================
// WIDE GEMM: 128x256 CTA, 8 warps, warp tile 64x64, BK=64, 2 stages x 96KB.
// qkv only (bias -> bf16 hi/lo).
// ===========================================================================
#define WSTG_BYTES 98304
#define WGEMM_SMEM (2 * WSTG_BYTES)

__device__ __forceinline__ void w_load_stage(
    uint32_t sbase,
    const __nv_bfloat16* __restrict__ Ah, const __nv_bfloat16* __restrict__ Al,
    const __nv_bfloat16* __restrict__ Bh, const __nv_bfloat16* __restrict__ Bl,
    int K, int k0, int tid)
{
    #pragma unroll
    for (int half = 0; half < 2; ++half) {
        const __nv_bfloat16* S = half ? Al : Ah;
        const uint32_t base = sbase + half * 16384;
        #pragma unroll
        for (int it = 0; it < 4; ++it) {
            const int i = tid + it * 256;
            const int row = i >> 3, c = i & 7;
            cpa16(base + (row << 7) + ((c ^ (row & 7)) << 4),
                  S + (size_t)row * K + k0 + c * 8);
        }
    }
    #pragma unroll
    for (int half = 0; half < 2; ++half) {
        const __nv_bfloat16* S = half ? Bl : Bh;
        const uint32_t base = sbase + 32768 + half * 32768;
        #pragma unroll
        for (int it = 0; it < 8; ++it) {
            const int i = tid + it * 256;
            const int row = i >> 3, c = i & 7;
            cpa16(base + (row << 7) + ((c ^ (row & 7)) << 4),
                  S + (size_t)row * K + k0 + c * 8);
        }
    }
    cpa_commit();
}

__global__ __launch_bounds__(256) void hmma_gemm_w(
    const __nv_bfloat16* __restrict__ Ah, const __nv_bfloat16* __restrict__ Al,
    const __nv_bfloat16* __restrict__ Bh, const __nv_bfloat16* __restrict__ Bl,
    const float* __restrict__ bias,
    __nv_bfloat16* __restrict__ Ch, __nv_bfloat16* __restrict__ Cl,
    int M, int N, int K)
{
    extern __shared__ char smem[];
    const uint32_t sb = smem_u32(smem);
    const int tid = threadIdx.x;
    const int wid = tid >> 5;
    const int lane = tid & 31;
    const int wm = wid >> 2;
    const int wn = wid & 3;
    const int bm = blockIdx.y * 128;
    const int bn = blockIdx.x * 256;

    const int nkk = K >> 6;

    Ah += (size_t)bm * K; Al += (size_t)bm * K;
    Bh += (size_t)bn * K; Bl += (size_t)bn * K;

    w_load_stage(sb, Ah, Al, Bh, Bl, K, 0, tid);
    w_load_stage(sb + WSTG_BYTES, Ah, Al, Bh, Bl, K, 64, tid);

    float acc[4][8][4];
    #pragma unroll
    for (int i = 0; i < 4; ++i)
        #pragma unroll
        for (int j = 0; j < 8; ++j)
            #pragma unroll
            for (int q = 0; q < 4; ++q) acc[i][j][q] = 0.0f;

    const int arow = wm * 64 + (lane & 15);
    const int akoff = (lane >> 4);
    const int brow = wn * 64 + (lane & 7) + ((lane >> 4) << 3);
    const int bkoff = ((lane >> 3) & 1);

    for (int kt = 0; kt < nkk; ++kt) {
        cpa_wait<1>();
        __syncthreads();

        const uint32_t sA  = sb + (uint32_t)(kt & 1) * WSTG_BYTES;
        const uint32_t sAl = sA + 16384;
        const uint32_t sBh = sA + 32768;
        const uint32_t sBl = sA + 65536;

        #pragma unroll
        for (int ks = 0; ks < 4; ++ks) {
            uint32_t afh[4][4], afl[4][4], bfh[8][2], bfl[8][2];
            const int kc = ks * 2 + akoff;
            #pragma unroll
            for (int mi = 0; mi < 4; ++mi) {
                const int r = arow + mi * 16;
                const uint32_t off = (r << 7) + ((kc ^ (r & 7)) << 4);
                ldsm_x4(afh[mi], sA + off);
                ldsm_x4(afl[mi], sAl + off);
            }
            const int kcb = ks * 2 + bkoff;
            #pragma unroll
            for (int p = 0; p < 4; ++p) {
                const int r = brow + p * 16;
                const uint32_t off = (r << 7) + ((kcb ^ (r & 7)) << 4);
                ldsm_x4p(bfh[p * 2], bfh[p * 2 + 1], sBh + off);
                ldsm_x4p(bfl[p * 2], bfl[p * 2 + 1], sBl + off);
            }
            #pragma unroll
            for (int ni = 0; ni < 8; ++ni)
                #pragma unroll
                for (int mi = 0; mi < 4; ++mi) {
                    mma_bf16(acc[mi][ni], afh[mi], bfh[ni]);
                    mma_bf16(acc[mi][ni], afh[mi], bfl[ni]);
                    mma_bf16(acc[mi][ni], afl[mi], bfh[ni]);
                }
        }

        __syncthreads();
        if (kt + 2 < nkk) {
            w_load_stage(sA, Ah, Al, Bh, Bl, K, (kt + 2) * 64, tid);
        } else {
            cpa_commit();
        }
    }

    const int grp = lane >> 2;
    const int tig = lane & 3;
    #pragma unroll
    for (int mi = 0; mi < 4; ++mi) {
        #pragma unroll
        for (int half = 0; half < 2; ++half) {
            const int grow = bm + wm * 64 + mi * 16 + grp + half * 8;
            #pragma unroll
            for (int ni = 0; ni < 8; ++ni) {
                const int gcol = bn + wn * 64 + ni * 8 + tig * 2;
                float v0 = acc[mi][ni][half * 2 + 0] + bias[gcol];
                float v1 = acc[mi][ni][half * 2 + 1] + bias[gcol + 1];
                __nv_bfloat16 h0 = __float2bfloat16(v0);
                __nv_bfloat16 h1 = __float2bfloat16(v1);
                __nv_bfloat162 hh, ll;
                hh.x = h0; hh.y = h1;
                ll.x = __float2bfloat16(v0 - __bfloat162float(h0));
                ll.y = __float2bfloat16(v1 - __bfloat162float(h1));
                *(__nv_bfloat162*)(Ch + (size_t)grow * N + gcol) = hh;
                *(__nv_bfloat162*)(Cl + (size_t)grow * N + gcol) = ll;
            }
        }
    }
}

// ===========================================================================
// NARROW GEMM: 128x128 CTA, 8 warps, warp tile 64x32, BK=64,
// 3 stages x 64KB, fragment double buffer.
// MODE: 1 bias+gelu->bf16 hi/lo   2 bias+residual->fp32
// ===========================================================================
#define NSTG_BYTES 65536
#define NGEMM_SMEM (3 * NSTG_BYTES)

__device__ __forceinline__ void n_load_stage(
    uint32_t sbase,
    const __nv_bfloat16* __restrict__ Ah, const __nv_bfloat16* __restrict__ Al,
    const __nv_bfloat16* __restrict__ Bh, const __nv_bfloat16* __restrict__ Bl,
    int K, int k0, int tid)
{
    const __nv_bfloat16* srcs[4] = { Ah, Al, Bh, Bl };
    #pragma unroll
    for (int t4 = 0; t4 < 4; ++t4) {
        const __nv_bfloat16* S = srcs[t4];
        const uint32_t base = sbase + t4 * 16384;
        #pragma unroll
        for (int it = 0; it < 4; ++it) {
            const int i = tid + it * 256;
            const int row = i >> 3, c = i & 7;
            cpa16(base + (row << 7) + ((c ^ (row & 7)) << 4),
                  S + (size_t)row * K + k0 + c * 8);
        }
    }
    cpa_commit();
}

template<int MODE>
__global__ __launch_bounds__(256, 1) void hmma_gemm_n(
    const __nv_bfloat16* __restrict__ Ah, const __nv_bfloat16* __restrict__ Al,
    const __nv_bfloat16* __restrict__ Bh, const __nv_bfloat16* __restrict__ Bl,
    const float* __restrict__ bias, const float* __restrict__ R,
    float* __restrict__ Cf, __nv_bfloat16* __restrict__ Ch,
    __nv_bfloat16* __restrict__ Cl, int M, int N, int K)
{
    extern __shared__ char smem[];
    const uint32_t sb = smem_u32(smem);
    const int tid = threadIdx.x;
    const int wid = tid >> 5;
    const int lane = tid & 31;
    const int wm = wid >> 2;
    const int wn = wid & 3;
    const int bm = blockIdx.y * 128;
    const int bn = blockIdx.x * 128;

    const int nkk = K >> 6;

    Ah += (size_t)bm * K; Al += (size_t)bm * K;
    Bh += (size_t)bn * K; Bl += (size_t)bn * K;

    n_load_stage(sb, Ah, Al, Bh, Bl, K, 0, tid);
    n_load_stage(sb + NSTG_BYTES, Ah, Al, Bh, Bl, K, 64, tid);

    float acc[4][4][4];
    #pragma unroll
    for (int i = 0; i < 4; ++i)
        #pragma unroll
        for (int j = 0; j < 4; ++j)
            #pragma unroll
            for (int q = 0; q < 4; ++q) acc[i][j][q] = 0.0f;

    const int arow = wm * 64 + (lane & 15);
    const int akoff = (lane >> 4);
    const int brow_base = wn * 32 + (lane & 7);
    const int bkoff = ((lane >> 3) & 1);

    uint32_t afh[2][4][4], afl[2][4][4], bfh[2][4][2], bfl[2][4][2];

    for (int kt = 0; kt < nkk; ++kt) {
        cpa_wait<1>();
        __syncthreads();

        if (kt + 2 < nkk) {
            n_load_stage(sb + (uint32_t)((kt + 2) % 3) * NSTG_BYTES,
                         Ah, Al, Bh, Bl, K, (kt + 2) * 64, tid);
        } else {
            cpa_commit();
        }

        const uint32_t sA  = sb + (uint32_t)(kt % 3) * NSTG_BYTES;
        const uint32_t sAl = sA + 16384;
        const uint32_t sBh = sA + 32768;
        const uint32_t sBl = sA + 49152;

        {
            const int kc = akoff;
            #pragma unroll
            for (int mi = 0; mi < 4; ++mi) {
                const int r = arow + mi * 16;
                const uint32_t off = (r << 7) + ((kc ^ (r & 7)) << 4);
                ldsm_x4(afh[0][mi], sA + off);
                ldsm_x4(afl[0][mi], sAl + off);
            }
            const int kcb = bkoff;
            #pragma unroll
            for (int ni = 0; ni < 4; ++ni) {
                const int r = brow_base + ni * 8;
                const uint32_t off = (r << 7) + ((kcb ^ (r & 7)) << 4);
                ldsm_x2(bfh[0][ni], sBh + off);
                ldsm_x2(bfl[0][ni], sBl + off);
            }
        }

        #pragma unroll
        for (int ks = 0; ks < 4; ++ks) {
            const int cur = ks & 1;
            if (ks < 3) {
                const int nxt = cur ^ 1;
                const int kc = (ks + 1) * 2 + akoff;
                #pragma unroll
                for (int mi = 0; mi < 4; ++mi) {
                    const int r = arow + mi * 16;
                    const uint32_t off = (r << 7) + ((kc ^ (r & 7)) << 4);
                    ldsm_x4(afh[nxt][mi], sA + off);
                    ldsm_x4(afl[nxt][mi], sAl + off);
                }
                const int kcb = (ks + 1) * 2 + bkoff;
                #pragma unroll
                for (int ni = 0; ni < 4; ++ni) {
                    const int r = brow_base + ni * 8;
                    const uint32_t off = (r << 7) + ((kcb ^ (r & 7)) << 4);
                    ldsm_x2(bfh[nxt][ni], sBh + off);
                    ldsm_x2(bfl[nxt][ni], sBl + off);
                }
            }
            #pragma unroll
            for (int ni = 0; ni < 4; ++ni)
                #pragma unroll
                for (int mi = 0; mi < 4; ++mi) {
                    mma_bf16(acc[mi][ni], afh[cur][mi], bfh[cur][ni]);
                    mma_bf16(acc[mi][ni], afh[cur][mi], bfl[cur][ni]);
                    mma_bf16(acc[mi][ni], afl[cur][mi], bfh[cur][ni]);
                }
        }
    }

    const int grp = lane >> 2;
    const int tig = lane & 3;
    #pragma unroll
    for (int mi = 0; mi < 4; ++mi) {
        #pragma unroll
        for (int half = 0; half < 2; ++half) {
            const int grow = bm + wm * 64 + mi * 16 + grp + half * 8;
            #pragma unroll
            for (int ni = 0; ni < 4; ++ni) {
                const int gcol = bn + wn * 32 + ni * 8 + tig * 2;
                float v0 = acc[mi][ni][half * 2 + 0] + bias[gcol];
                float v1 = acc[mi][ni][half * 2 + 1] + bias[gcol + 1];
                if (MODE == 2) {
                    float2 rr = *(const float2*)(R + (size_t)grow * N + gcol);
                    *(float2*)(Cf + (size_t)grow * N + gcol) =
                        make_float2(v0 + rr.x, v1 + rr.y);
                } else {
                    v0 = gelu_exact(v0); v1 = gelu_exact(v1);
                    __nv_bfloat16 h0 = __float2bfloat16(v0);
                    __nv_bfloat16 h1 = __float2bfloat16(v1);
                    __nv_bfloat162 hh, ll;
                    hh.x = h0; hh.y = h1;
                    ll.x = __float2bfloat16(v0 - __bfloat162float(h0));
                    ll.y = __float2bfloat16(v1 - __bfloat162float(h1));
                    *(__nv_bfloat162*)(Ch + (size_t)grow * N + gcol) = hh;
                    *(__nv_bfloat162*)(Cl + (size_t)grow * N + gcol) = ll;
                }
            }
        }
    }
}

// ---------------------------------------------------------------------------
// HMMA flash attention (round-4 double-buffered config). Heavy q-tiles first.
// ---------------------------------------------------------------------------
#define ATT_SMEM (16384 + 2 * 32768)

__device__ __forceinline__ void attn_stage_load(
    uint32_t sbase, const __nv_bfloat16* __restrict__ qh,
    const __nv_bfloat16* __restrict__ ql, int growbase, int colbase, int tid)
{
    #pragma unroll
    for (int it = 0; it < 16; ++it) {
        const int i = tid + it * 128;
        const int tile = i >> 9;
        const int r = (i >> 3) & 63;
        const int c = i & 7;
        const __nv_bfloat16* arr = (tile & 1) ? ql : qh;
        const int seg = (tile >> 1) ? 2 * EDIM : 0;
        cpa16(sbase + tile * 8192 + (r << 7) + ((c ^ (r & 7)) << 4),
              arr + (size_t)(growbase + r) * E3 + seg + colbase + c * 8);
    }
}

__global__ __launch_bounds__(128, 2) void attn_kernel(
    const __nv_bfloat16* __restrict__ qh, const __nv_bfloat16* __restrict__ ql,
    __nv_bfloat16* __restrict__ yh, __nv_bfloat16* __restrict__ yl)
{
    extern __shared__ char smem[];
    const uint32_t sb = smem_u32(smem);
    const int tid = threadIdx.x;
    const int w = tid >> 5;
    const int lane = tid & 31;
    const int qt = gridDim.x - 1 - blockIdx.x;
    const int bh = blockIdx.y;
    const int b = bh / NHEAD;
    const int hh = bh % NHEAD;
    const int colbase = hh * HDIM;
    const int qrowbase = b * TSEQ + qt * 64;

    #pragma unroll
    for (int it = 0; it < 8; ++it) {
        const int i = tid + it * 128;
        const int tile = i >> 9;
        const int r = (i >> 3) & 63;
        const int c = i & 7;
        const __nv_bfloat16* arr = tile ? ql : qh;
        cpa16(sb + tile * 8192 + (r << 7) + ((c ^ (r & 7)) << 4),
              arr + (size_t)(qrowbase + r) * E3 + EDIM + colbase + c * 8);
    }
    attn_stage_load(sb + 16384, qh, ql, b * TSEQ, colbase, tid);
    cpa_commit();

    uint32_t qfh[4][4], qfl[4][4];
    float o[8][4];
    #pragma unroll
    for (int ni = 0; ni < 8; ++ni)
        #pragma unroll
        for (int q = 0; q < 4; ++q) o[ni][q] = 0.0f;
    float m0 = -1e30f, m1 = -1e30f, l0 = 0.0f, l1 = 0.0f;

    const uint32_t stg[2] = { sb + 16384, sb + 16384 + 32768 };
    const int rl0 = w * 16 + (lane >> 2);
    const int cl0 = (lane & 3) * 2;

    for (int kt = 0; kt <= qt; ++kt) {
        if (kt + 1 <= qt)
            attn_stage_load(stg[(kt + 1) & 1], qh, ql,
                            b * TSEQ + (kt + 1) * 64, colbase, tid);
        cpa_commit();
        cpa_wait<1>();
        __syncthreads();

        if (kt == 0) {
            const int r = w * 16 + (lane & 15);
            #pragma unroll
            for (int ks = 0; ks < 4; ++ks) {
                const int kc = ks * 2 + (lane >> 4);
                const uint32_t off = (r << 7) + ((kc ^ (r & 7)) << 4);
                ldsm_x4(qfh[ks], sb + off);
                ldsm_x4(qfl[ks], sb + 8192 + off);
            }
        }

        const uint32_t sKh = stg[kt & 1];
        const uint32_t sKl = sKh + 8192;
        const uint32_t sVh = sKh + 16384;
        const uint32_t sVl = sKh + 24576;

        float s[8][4];
        #pragma unroll
        for (int ni = 0; ni < 8; ++ni)
            #pragma unroll
            for (int q = 0; q < 4; ++q) s[ni][q] = 0.0f;

        #pragma unroll
        for (int ks = 0; ks < 4; ++ks) {
            const int kcb = ks * 2 + ((lane >> 3) & 1);
            #pragma unroll
            for (int ni = 0; ni < 8; ++ni) {
                const int r = ni * 8 + (lane & 7);
                const uint32_t off = (r << 7) + ((kcb ^ (r & 7)) << 4);
                uint32_t kfh[2], kfl[2];
                ldsm_x2(kfh, sKh + off);
                ldsm_x2(kfl, sKl + off);
                mma_bf16(s[ni], qfh[ks], kfh);
                mma_bf16(s[ni], qfh[ks], kfl);
                mma_bf16(s[ni], qfl[ks], kfh);
            }
        }

        if (kt == qt) {
            #pragma unroll
            for (int ni = 0; ni < 8; ++ni) {
                const int c0 = ni * 8 + cl0;
                if (c0 > rl0)     s[ni][0] = -1e30f;
                if (c0 + 1 > rl0) s[ni][1] = -1e30f;
                if (c0 > rl0 + 8)     s[ni][2] = -1e30f;
                if (c0 + 1 > rl0 + 8) s[ni][3] = -1e30f;
            }
        }

        float mx0 = -1e30f, mx1 = -1e30f;
        #pragma unroll
        for (int ni = 0; ni < 8; ++ni) {
            mx0 = fmaxf(mx0, fmaxf(s[ni][0], s[ni][1]));
            mx1 = fmaxf(mx1, fmaxf(s[ni][2], s[ni][3]));
        }
        mx0 = fmaxf(mx0, __shfl_xor_sync(0xffffffffu, mx0, 1, 4));
        mx0 = fmaxf(mx0, __shfl_xor_sync(0xffffffffu, mx0, 2, 4));
        mx1 = fmaxf(mx1, __shfl_xor_sync(0xffffffffu, mx1, 1, 4));
        mx1 = fmaxf(mx1, __shfl_xor_sync(0xffffffffu, mx1, 2, 4));
        const float nm0 = fmaxf(m0, mx0), nm1 = fmaxf(m1, mx1);
        const float al0 = __expf(m0 - nm0), al1 = __expf(m1 - nm1);
        float rs0 = 0.0f, rs1 = 0.0f;
        #pragma unroll
        for (int ni = 0; ni < 8; ++ni) {
            s[ni][0] = __expf(s[ni][0] - nm0); rs0 += s[ni][0];
            s[ni][1] = __expf(s[ni][1] - nm0); rs0 += s[ni][1];
            s[ni][2] = __expf(s[ni][2] - nm1); rs1 += s[ni][2];
            s[ni][3] = __expf(s[ni][3] - nm1); rs1 += s[ni][3];
        }
        rs0 += __shfl_xor_sync(0xffffffffu, rs0, 1, 4);
        rs0 += __shfl_xor_sync(0xffffffffu, rs0, 2, 4);
        rs1 += __shfl_xor_sync(0xffffffffu, rs1, 1, 4);
        rs1 += __shfl_xor_sync(0xffffffffu, rs1, 2, 4);
        l0 = l0 * al0 + rs0; m0 = nm0;
        l1 = l1 * al1 + rs1; m1 = nm1;
        #pragma unroll
        for (int ni = 0; ni < 8; ++ni) {
            o[ni][0] *= al0; o[ni][1] *= al0;
            o[ni][2] *= al1; o[ni][3] *= al1;
        }

        uint32_t pah[4][4], pal[4][4];
        #pragma unroll
        for (int kc = 0; kc < 4; ++kc) {
            #pragma unroll
            for (int half = 0; half < 2; ++half) {
                const int ni = kc * 2 + half;
                #pragma unroll
                for (int pr = 0; pr < 2; ++pr) {
                    float p0 = s[ni][pr * 2 + 0];
                    float p1 = s[ni][pr * 2 + 1];
                    __nv_bfloat16 h0 = __float2bfloat16(p0);
                    __nv_bfloat16 h1 = __float2bfloat16(p1);
                    __nv_bfloat162 hh, ll;
                    hh.x = h0; hh.y = h1;
                    ll.x = __float2bfloat16(p0 - __bfloat162float(h0));
                    ll.y = __float2bfloat16(p1 - __bfloat162float(h1));
                    pah[kc][half * 2 + pr] = *(uint32_t*)&hh;
                    pal[kc][half * 2 + pr] = *(uint32_t*)&ll;
                }
            }
        }

        #pragma unroll
        for (int kc = 0; kc < 4; ++kc) {
            const int rV = kc * 16 + (lane & 15);
            #pragma unroll
            for (int ni = 0; ni < 8; ++ni) {
                const uint32_t off = (rV << 7) + ((ni ^ (rV & 7)) << 4);
                uint32_t vfh[2], vfl[2];
                ldsm_x2t(vfh, sVh + off);
                ldsm_x2t(vfl, sVl + off);
                mma_bf16(o[ni], pah[kc], vfh);
                mma_bf16(o[ni], pah[kc], vfl);
                mma_bf16(o[ni], pal[kc], vfh);
            }
        }
        __syncthreads();
    }

    const float il0 = 1.0f / l0, il1 = 1.0f / l1;
    const size_t row0 = (size_t)(qrowbase + rl0) * EDIM + colbase + cl0;
    const size_t row1 = (size_t)(qrowbase + rl0 + 8) * EDIM + colbase + cl0;
    #pragma unroll
    for (int ni = 0; ni < 8; ++ni) {
        const int dc = ni * 8;
        float v0 = o[ni][0] * il0, v1 = o[ni][1] * il0;
        float v2 = o[ni][2] * il1, v3 = o[ni][3] * il1;
        __nv_bfloat16 h0 = __float2bfloat16(v0), h1 = __float2bfloat16(v1);
        __nv_bfloat16 h2 = __float2bfloat16(v2), h3 = __float2bfloat16(v3);
        __nv_bfloat162 a, bb, c, d;
        a.x = h0; a.y = h1; c.x = h2; c.y = h3;
        bb.x = __float2bfloat16(v0 - __bfloat162float(h0));
        bb.y = __float2bfloat16(v1 - __bfloat162float(h1));
        d.x = __float2bfloat16(v2 - __bfloat162float(h2));
        d.y = __float2bfloat16(v3 - __bfloat162float(h3));
        *(__nv_bfloat162*)(yh + row0 + dc) = a;
        *(__nv_bfloat162*)(yl + row0 + dc) = bb;
        *(__nv_bfloat162*)(yh + row1 + dc) = c;
        *(__nv_bfloat162*)(yl + row1 + dc) = d;
    }
}

// ---------------------------------------------------------------------------
// lm_head
// ---------------------------------------------------------------------------
__global__ __launch_bounds__(256) void logits_kernel(
    const float* __restrict__ xf, const float* __restrict__ wte,
    const float* __restrict__ lm_b, float* __restrict__ out)
{
    __shared__ float xs[NBATCH * EDIM];
    for (int i = threadIdx.x; i < NBATCH * EDIM; i += 256) xs[i] = xf[i];
    __syncthreads();

    const int warp = threadIdx.x >> 5;
    const int lane = threadIdx.x & 31;
    const int v = blockIdx.x * 8 + warp;

    const float* wrow = wte + (size_t)v * EDIM;
    float acc[NBATCH];
    #pragma unroll
    for (int b = 0; b < NBATCH; ++b) acc[b] = 0.0f;

    for (int k4 = lane * 4; k4 < EDIM; k4 += 128) {
        float4 wv = *(const float4*)(wrow + k4);
        #pragma unroll
        for (int b = 0; b < NBATCH; ++b) {
            float4 xv = *(const float4*)(xs + b * EDIM + k4);
            acc[b] += wv.x*xv.x + wv.y*xv.y + wv.z*xv.z + wv.w*xv.w;
        }
    }
    #pragma unroll
    for (int o = 16; o; o >>= 1)
        #pragma unroll
        for (int b = 0; b < NBATCH; ++b)
            acc[b] += __shfl_xor_sync(0xffffffffu, acc[b], o);

    if (lane == 0) {
        const float bb = lm_b[v];
        #pragma unroll
        for (int b = 0; b < NBATCH; ++b)
            out[(size_t)b * VOCAB + v] = acc[b] + bb;
    }
}

// ---------------------------------------------------------------------------
// Launcher
// ---------------------------------------------------------------------------
extern "C" void kernel_launch(void* const* d_in, const int* in_sizes, int n_in,
                              void* d_out, int out_size)
{
    (void)in_sizes; (void)n_in; (void)out_size;
    const int*   idx    = (const int*)  d_in[0];
    const float* wte    = (const float*)d_in[1];
    const float* wpe    = (const float*)d_in[2];
    const float* qkv_w  = (const float*)d_in[3];
    const float* qkv_b  = (const float*)d_in[4];
    const float* proj_w = (const float*)d_in[5];
    const float* proj_b = (const float*)d_in[6];
    const float* ln_w   = (const float*)d_in[7];
    const float* ln_b   = (const float*)d_in[8];
    const float* c1_w   = (const float*)d_in[9];
    const float* c1_b   = (const float*)d_in[10];
    const float* c2_w   = (const float*)d_in[11];
    const float* c2_b   = (const float*)d_in[12];
    const float* lnf_w  = (const float*)d_in[13];
    const float* lnf_b  = (const float*)d_in[14];
    const float* lm_b   = (const float*)d_in[15];
    float* out = (float*)d_out;

    float *x, *xf;
    __nv_bfloat16 *h_hi, *h_lo, *qv_h, *qv_l, *att_hi, *att_lo, *a1_hi, *a1_lo;
    __nv_bfloat16 *wq_h, *wq_l, *wp_h, *wp_l, *w1_h, *w1_l, *w2_h, *w2_l;
    cudaGetSymbolAddress((void**)&x,     g_x);
    cudaGetSymbolAddress((void**)&xf,    g_xf);
    cudaGetSymbolAddress((void**)&h_hi,  g_h_hi);
    cudaGetSymbolAddress((void**)&h_lo,  g_h_lo);
    cudaGetSymbolAddress((void**)&qv_h,  g_qkv_hi);
    cudaGetSymbolAddress((void**)&qv_l,  g_qkv_lo);
    cudaGetSymbolAddress((void**)&att_hi,g_att_hi);
    cudaGetSymbolAddress((void**)&att_lo,g_att_lo);
    cudaGetSymbolAddress((void**)&a1_hi, g_a1_hi);
    cudaGetSymbolAddress((void**)&a1_lo, g_a1_lo);
    cudaGetSymbolAddress((void**)&wq_h,  g_wqkv_hi);
    cudaGetSymbolAddress((void**)&wq_l,  g_wqkv_lo);
    cudaGetSymbolAddress((void**)&wp_h,  g_wprj_hi);
    cudaGetSymbolAddress((void**)&wp_l,  g_wprj_lo);
    cudaGetSymbolAddress((void**)&w1_h,  g_wc1_hi);
    cudaGetSymbolAddress((void**)&w1_l,  g_wc1_lo);
    cudaGetSymbolAddress((void**)&w2_h,  g_wc2_hi);
    cudaGetSymbolAddress((void**)&w2_l,  g_wc2_lo);

    cudaFuncSetAttribute(attn_kernel,
        cudaFuncAttributeMaxDynamicSharedMemorySize, ATT_SMEM);
    cudaFuncSetAttribute(hmma_gemm_w,
        cudaFuncAttributeMaxDynamicSharedMemorySize, WGEMM_SMEM);
    cudaFuncSetAttribute(hmma_gemm_n<1>,
        cudaFuncAttributeMaxDynamicSharedMemorySize, NGEMM_SMEM);
    cudaFuncSetAttribute(hmma_gemm_n<2>,
        cudaFuncAttributeMaxDynamicSharedMemorySize, NGEMM_SMEM);

    cvt_all_kernel<<<(CVT_TOTAL + 255) / 256, 256>>>(
        qkv_w, wq_h, wq_l, proj_w, wp_h, wp_l,
        c1_w, w1_h, w1_l, c2_w, w2_h, w2_l);

    embed_kernel<<<NTOK, 192>>>(idx, wte, wpe, x);

    for (int l = 0; l < NLAYER; ++l) {
        const float* lw = ln_w + l * EDIM;
        const float* lb = ln_b + l * EDIM;
        const size_t oq = (size_t)l * E3 * EDIM;
        const size_t op = (size_t)l * EDIM * EDIM;
        const size_t o1 = (size_t)l * E4 * EDIM;

        ln_kernel<1><<<NTOK, 192>>>(x, lw, lb, nullptr, h_hi, h_lo, 1, 0);
        hmma_gemm_w<<<dim3(E3 / 256, NTOK / 128), 256, WGEMM_SMEM>>>(
            h_hi, h_lo, wq_h + oq, wq_l + oq, qkv_b + (size_t)l * E3,
            qv_h, qv_l, NTOK, E3, EDIM);
        attn_kernel<<<dim3(TSEQ / 64, NBATCH * NHEAD), 128, ATT_SMEM>>>(
            qv_h, qv_l, att_hi, att_lo);
        hmma_gemm_n<2><<<dim3(EDIM / 128, NTOK / 128), 256, NGEMM_SMEM>>>(
            att_hi, att_lo, wp_h + op, wp_l + op, proj_b + (size_t)l * EDIM,
            x, x, nullptr, nullptr, NTOK, EDIM, EDIM);

        ln_kernel<1><<<NTOK, 192>>>(x, lw, lb, nullptr, h_hi, h_lo, 1, 0);
        hmma_gemm_n<1><<<dim3(E4 / 128, NTOK / 128), 256, NGEMM_SMEM>>>(
            h_hi, h_lo, w1_h + o1, w1_l + o1, c1_b + (size_t)l * E4,
            nullptr, nullptr, a1_hi, a1_lo, NTOK, E4, EDIM);
        hmma_gemm_n<2><<<dim3(EDIM / 128, NTOK / 128), 256, NGEMM_SMEM>>>(
            a1_hi, a1_lo, w2_h + o1, w2_l + o1, c2_b + (size_t)l * EDIM,
            x, x, nullptr, nullptr, NTOK, EDIM, E4);
    }

    ln_kernel<0><<<NBATCH, 192>>>(x, lnf_w, lnf_b, xf, nullptr, nullptr,
                                  TSEQ, TSEQ - 1);
    logits_kernel<<<VOCAB / 8, 256>>>(xf, wte, lm_b, out);
}